// round 12
// baseline (speedup 1.0000x reference)
#include <cuda_runtime.h>
#include <cuda_bf16.h>
#include <math.h>
#include <stdint.h>

// ---------------- problem constants ----------------
constexpr int N_   = 20000;   // nodes
constexpr int E_   = 100000;  // edges
constexpr int D_   = 248;     // Lie algebra dim
constexpr int HID_ = 256;     // MLP hidden
constexpr int IN_  = 128;     // input feature dim
constexpr int OUT_ = 16;      // output dim
constexpr int NL_  = 4;       // layers
constexpr int NNZ_ = 512;     // structure constant nnz
constexpr int NB_  = 1024;    // killing form nnz
constexpr int NG_  = 128;     // graphs
constexpr int D2_  = 2 * D_;  // 496
constexpr int DP1_ = D_ + 1;  // 249

// ---------------- scratch (device globals; allocation is forbidden) ----------------
__device__ float g_t1[(size_t)N_ * HID_];    // node hidden / hw staging
__device__ float g_h[(size_t)N_ * D_];       // node features h
__device__ float g_br[(size_t)E_ * D_];      // per-edge Lie bracket
__device__ float g_eH[(size_t)E_ * HID_];    // edge hidden
__device__ float g_agg[(size_t)N_ * D_];     // aggregated messages
__device__ float g_pooled[NG_ * DP1_];
__device__ float g_cnt[NG_];
__device__ float g_zbias[HID_];              // zero bias for split GEMM

// k-sorted structure constants (built per launch by sort_sc_kernel)
__device__ int   g_scOff[D_ + 1];
__device__ int   g_scSI[NNZ_];
__device__ int   g_scSJ[NNZ_];
__device__ float g_scSC[NNZ_];

__device__ __forceinline__ float silu_f(float v) {
    return v / (1.0f + expf(-v));
}

__device__ __forceinline__ uint32_t pack_bf16(float a, float b) {
    __nv_bfloat162 t = __floats2bfloat162_rn(a, b);   // a -> low, b -> high
    return *(uint32_t*)&t;
}
__device__ __forceinline__ float bf16_round(float x) {
    return __bfloat162float(__float2bfloat16(x));
}

// ---------------- 3xBF16 tensor-core GEMM, double-buffered, split-K A ----------------
// C = act(A @ W + bias + res)   OR  (scatter mode, dstIdx != null):
//     atomicAdd(C[dstIdx[m] * N + n], (A@W + bias)[m,n])
// Residual added BEFORE activation; residual row = resIdx[m] if resIdx != null else m.
// A cols [0,K1) from A1 (row gathered via gidx if non-null, stride K1);
// A cols [K1,K) from A2 (direct row, stride K-K1).
// W: K x N row-major. Requires K % 8 == 0, K1 % 8 == 0, N % 4 == 0.
constexpr int BM = 128, BN = 128, BK = 16;
constexpr int PA = 12;
constexpr int PW = 136;

__global__ __launch_bounds__(256, 2) void gemm_3xbf16(
    const float* __restrict__ A1, const int* __restrict__ gidx,
    const float* __restrict__ A2, int K1,
    const float* __restrict__ W, const float* __restrict__ bias,
    const float* __restrict__ res, const int* __restrict__ resIdx,
    const int* __restrict__ dstIdx,
    float* __restrict__ C, int M, int N, int K, int act)
{
    __shared__ uint32_t AsH[2][BM][PA];
    __shared__ uint32_t AsL[2][BM][PA];
    __shared__ uint32_t WsH[2][8][PW];
    __shared__ uint32_t WsL[2][8][PW];

    const int tid  = threadIdx.x;
    const int lane = tid & 31;
    const int wid  = tid >> 5;
    const int row0 = blockIdx.y * BM;
    const int col0 = blockIdx.x * BN;

    const int aRow = tid >> 1;
    const int aK8  = (tid & 1) * 8;
    const int wKr  = (tid >> 5) * 2;
    const int wCol = lane * 4;

    const int K2s = K - K1;

    const int gRowA = row0 + aRow;
    const bool av = gRowA < M;
    size_t a1off = 0, a2off = 0;
    if (av) {
        int r = gidx ? __ldg(&gidx[gRowA]) : gRowA;
        a1off = (size_t)r * K1;
        a2off = (size_t)gRowA * K2s;
    }
    const int gnW = col0 + wCol;
    const bool wv = gnW < N;

    const int wm = (wid & 3) * 32;
    const int wn = (wid >> 2) * 64;
    const int grp = lane >> 2;
    const int qid = lane & 3;

    float acc[2][8][4];
    #pragma unroll
    for (int mt = 0; mt < 2; mt++)
        #pragma unroll
        for (int nt = 0; nt < 8; nt++)
            #pragma unroll
            for (int c = 0; c < 4; c++) acc[mt][nt][c] = 0.0f;

    auto loadA4 = [&](int kg) -> float4 {
        if (!av || kg >= K) return make_float4(0.f, 0.f, 0.f, 0.f);
        if (kg < K1) return *(const float4*)&A1[a1off + kg];
        return *(const float4*)&A2[a2off + (kg - K1)];
    };
    auto loadW4 = [&](int krow) -> float4 {
        if (!wv || krow >= K) return make_float4(0.f, 0.f, 0.f, 0.f);
        return *(const float4*)&W[(size_t)krow * N + gnW];
    };

    float4 aV0, aV1, wV0, wV1;
    auto prefetch = [&](int k0) {
        aV0 = loadA4(k0 + aK8);
        aV1 = loadA4(k0 + aK8 + 4);
        wV0 = loadW4(k0 + wKr);
        wV1 = loadW4(k0 + wKr + 1);
    };
    auto stage = [&](int buf) {
        float h0 = bf16_round(aV0.x), h1 = bf16_round(aV0.y),
              h2 = bf16_round(aV0.z), h3 = bf16_round(aV0.w),
              h4 = bf16_round(aV1.x), h5 = bf16_round(aV1.y),
              h6 = bf16_round(aV1.z), h7 = bf16_round(aV1.w);
        uint4 hi = make_uint4(pack_bf16(h0, h1), pack_bf16(h2, h3),
                              pack_bf16(h4, h5), pack_bf16(h6, h7));
        uint4 lo = make_uint4(pack_bf16(aV0.x - h0, aV0.y - h1),
                              pack_bf16(aV0.z - h2, aV0.w - h3),
                              pack_bf16(aV1.x - h4, aV1.y - h5),
                              pack_bf16(aV1.z - h6, aV1.w - h7));
        *(uint4*)&AsH[buf][aRow][aK8 / 2] = hi;
        *(uint4*)&AsL[buf][aRow][aK8 / 2] = lo;
        float g0 = bf16_round(wV0.x), g1 = bf16_round(wV0.y),
              g2 = bf16_round(wV0.z), g3 = bf16_round(wV0.w),
              g4 = bf16_round(wV1.x), g5 = bf16_round(wV1.y),
              g6 = bf16_round(wV1.z), g7 = bf16_round(wV1.w);
        uint4 whi = make_uint4(pack_bf16(g0, g4), pack_bf16(g1, g5),
                               pack_bf16(g2, g6), pack_bf16(g3, g7));
        uint4 wlo = make_uint4(pack_bf16(wV0.x - g0, wV1.x - g4),
                               pack_bf16(wV0.y - g1, wV1.y - g5),
                               pack_bf16(wV0.z - g2, wV1.z - g6),
                               pack_bf16(wV0.w - g3, wV1.w - g7));
        *(uint4*)&WsH[buf][wKr / 2][wCol] = whi;
        *(uint4*)&WsL[buf][wKr / 2][wCol] = wlo;
    };

    const int nTiles = (K + BK - 1) / BK;
    prefetch(0);
    stage(0);
    if (nTiles > 1) prefetch(BK);
    __syncthreads();

    for (int t = 0; t < nTiles; t++) {
        const int buf = t & 1;
        if (t + 1 < nTiles) stage(buf ^ 1);
        if (t + 2 < nTiles) prefetch((t + 2) * BK);

        uint32_t ah[2][4], al[2][4];
        #pragma unroll
        for (int mt = 0; mt < 2; mt++) {
            const int ar = wm + 16 * mt + grp;
            ah[mt][0] = AsH[buf][ar    ][qid];
            ah[mt][1] = AsH[buf][ar + 8][qid];
            ah[mt][2] = AsH[buf][ar    ][qid + 4];
            ah[mt][3] = AsH[buf][ar + 8][qid + 4];
            al[mt][0] = AsL[buf][ar    ][qid];
            al[mt][1] = AsL[buf][ar + 8][qid];
            al[mt][2] = AsL[buf][ar    ][qid + 4];
            al[mt][3] = AsL[buf][ar + 8][qid + 4];
        }
        #pragma unroll
        for (int nt = 0; nt < 8; nt++) {
            const int bc = wn + 8 * nt + grp;
            uint32_t bh0 = WsH[buf][qid    ][bc];
            uint32_t bh1 = WsH[buf][qid + 4][bc];
            uint32_t bl0 = WsL[buf][qid    ][bc];
            uint32_t bl1 = WsL[buf][qid + 4][bc];
            #pragma unroll
            for (int mt = 0; mt < 2; mt++) {
                #define MMA_BF16(Afr, B0, B1)                                          \
                    asm volatile(                                                      \
                        "mma.sync.aligned.m16n8k16.row.col.f32.bf16.bf16.f32 "         \
                        "{%0,%1,%2,%3}, {%4,%5,%6,%7}, {%8,%9}, {%0,%1,%2,%3};"        \
                        : "+f"(acc[mt][nt][0]), "+f"(acc[mt][nt][1]),                  \
                          "+f"(acc[mt][nt][2]), "+f"(acc[mt][nt][3])                   \
                        : "r"(Afr[mt][0]), "r"(Afr[mt][1]),                            \
                          "r"(Afr[mt][2]), "r"(Afr[mt][3]),                            \
                          "r"(B0), "r"(B1))
                MMA_BF16(ah, bh0, bh1);
                MMA_BF16(al, bh0, bh1);
                MMA_BF16(ah, bl0, bl1);
                #undef MMA_BF16
            }
        }
        __syncthreads();
    }

    #pragma unroll
    for (int mt = 0; mt < 2; mt++) {
        #pragma unroll
        for (int rr = 0; rr < 2; rr++) {
            const int gm = row0 + wm + 16 * mt + grp + rr * 8;
            if (gm >= M) continue;
            int drow = 0;
            if (dstIdx) drow = __ldg(&dstIdx[gm]);
            size_t resRow = 0;
            if (res) resRow = (size_t)(resIdx ? __ldg(&resIdx[gm]) : gm) * N;
            #pragma unroll
            for (int nt = 0; nt < 8; nt++) {
                const int gn = col0 + wn + 8 * nt + qid * 2;
                if (gn >= N) continue;
                float2 bb = __ldg((const float2*)&bias[gn]);
                float v0 = acc[mt][nt][rr * 2 + 0] + bb.x;
                float v1 = acc[mt][nt][rr * 2 + 1] + bb.y;
                if (res) {
                    float2 rv = *(const float2*)&res[resRow + gn];
                    v0 += rv.x; v1 += rv.y;
                }
                if (act) { v0 = silu_f(v0); v1 = silu_f(v1); }
                if (dstIdx) {
                    atomicAdd(&C[(size_t)drow * N + gn],     v0);
                    atomicAdd(&C[(size_t)drow * N + gn + 1], v1);
                } else {
                    *(float2*)&C[(size_t)gm * N + gn] = make_float2(v0, v1);
                }
            }
        }
    }
}

// ---------------- structure-constant sort by k (1 block, per launch) ----------------
__global__ __launch_bounds__(256) void sort_sc_kernel(
    const int* __restrict__ sci, const int* __restrict__ scj,
    const int* __restrict__ sck, const float* __restrict__ scc)
{
    __shared__ int cnt[D_ + 1];
    __shared__ int cur[D_];
    const int tid = threadIdx.x;
    for (int k = tid; k <= D_; k += 256) cnt[k] = 0;
    __syncthreads();
    for (int t = tid; t < NNZ_; t += 256)
        atomicAdd(&cnt[__ldg(&sck[t])], 1);
    __syncthreads();
    if (tid == 0) {            // exclusive prefix over 248 bins (trivial size)
        int run = 0;
        for (int k = 0; k < D_; k++) {
            int c = cnt[k];
            g_scOff[k] = run;
            cur[k] = run;
            run += c;
        }
        g_scOff[D_] = run;
    }
    __syncthreads();
    for (int t = tid; t < NNZ_; t += 256) {
        int k = __ldg(&sck[t]);
        int p = atomicAdd(&cur[k], 1);
        g_scSI[p] = __ldg(&sci[t]);
        g_scSJ[p] = __ldg(&scj[t]);
        g_scSC[p] = __ldg(&scc[t]);
    }
}

// ---------------- edge bracket v2: k-sorted bins, no atomics ----------------
constexpr int EPB = 8;
__global__ __launch_bounds__(256) void edge_bracket_kernel(
    const float* __restrict__ h, const int* __restrict__ ei,
    float* __restrict__ br)
{
    // NOTE: 16B-aligned float tiles FIRST, then scalar index arrays (s_off padded
    // to 256 anyway). R11's fault was hs losing 16B alignment behind s_off[249].
    __shared__ alignas(16) float hs[EPB][D_];
    __shared__ alignas(16) float hd[EPB][D_];
    __shared__ alignas(16) float brs[EPB][D_];
    __shared__ int   s_i[NNZ_], s_j[NNZ_];
    __shared__ float s_c[NNZ_];
    __shared__ int   s_off[256];

    const int tid = threadIdx.x;
    for (int t = tid; t < NNZ_; t += 256) {
        s_i[t] = g_scSI[t];
        s_j[t] = g_scSJ[t];
        s_c[t] = g_scSC[t];
    }
    for (int k = tid; k < 256; k += 256)
        s_off[k] = (k <= D_) ? g_scOff[k] : g_scOff[D_];
    __syncthreads();

    const int w = tid >> 5, lane = tid & 31;
    const int e = blockIdx.x * EPB + w;
    if (e >= E_) return;
    const int s = __ldg(&ei[e]);
    const int d = __ldg(&ei[E_ + e]);

    const float4* hsrc = (const float4*)(h + (size_t)s * D_);
    const float4* hdst = (const float4*)(h + (size_t)d * D_);
    #pragma unroll
    for (int q = lane; q < D_ / 4; q += 32) {
        ((float4*)hs[w])[q] = hsrc[q];
        ((float4*)hd[w])[q] = hdst[q];
    }
    __syncwarp();

    // each lane owns k = lane, lane+32, ... : serial sum over its bin, no atomics
    #pragma unroll
    for (int k = lane; k < D_; k += 32) {
        const int b0 = s_off[k], b1 = s_off[k + 1];
        float sum = 0.0f;
        for (int t = b0; t < b1; t++)
            sum = fmaf(s_c[t], hs[w][s_i[t]] * hd[w][s_j[t]], sum);
        brs[w][k] = sum;
    }
    __syncwarp();

    float4* row = (float4*)(br + (size_t)e * D_);
    #pragma unroll
    for (int q = lane; q < D_ / 4; q += 32)
        row[q] = ((const float4*)brs[w])[q];
}

__global__ void zero_kernel(float* __restrict__ p, size_t n) {
    size_t idx = (size_t)blockIdx.x * blockDim.x + threadIdx.x;
    if (idx < n) p[idx] = 0.0f;
}

// ---------------- killing form + pooling (scatter to graphs) ----------------
__global__ __launch_bounds__(128) void killing_pool_kernel(
    const float* __restrict__ h, const int* __restrict__ batch,
    const int* __restrict__ kbr, const int* __restrict__ kbc,
    const float* __restrict__ kbv,
    float* __restrict__ pooled, float* __restrict__ cnt)
{
    const int n = blockIdx.x;
    __shared__ float hrow[D_];
    __shared__ float wsum[4];
    for (int k = threadIdx.x; k < D_; k += 128)
        hrow[k] = h[(size_t)n * D_ + k];
    __syncthreads();

    float s = 0.0f;
    for (int t = threadIdx.x; t < NB_; t += 128)
        s += __ldg(&kbv[t]) * hrow[__ldg(&kbr[t])] * hrow[__ldg(&kbc[t])];
    #pragma unroll
    for (int off = 16; off > 0; off >>= 1)
        s += __shfl_down_sync(0xffffffffu, s, off);
    if ((threadIdx.x & 31) == 0) wsum[threadIdx.x >> 5] = s;
    __syncthreads();

    const int b = __ldg(&batch[n]);
    for (int k = threadIdx.x; k < D_; k += 128)
        atomicAdd(&pooled[b * DP1_ + k], hrow[k]);
    if (threadIdx.x == 0) {
        float ks = wsum[0] + wsum[1] + wsum[2] + wsum[3];
        atomicAdd(&pooled[b * DP1_ + D_], ks);
        atomicAdd(&cnt[b], 1.0f);
    }
}

// ---------------- final MLP per graph ----------------
__global__ __launch_bounds__(256) void final_mlp_kernel(
    const float* __restrict__ pooled, const float* __restrict__ cnt,
    const float* __restrict__ Wo1, const float* __restrict__ bo1,
    const float* __restrict__ Wo2, const float* __restrict__ bo2,
    float* __restrict__ out)
{
    const int g = blockIdx.x;
    __shared__ float p[DP1_];
    __shared__ float hid[HID_];
    const float c = fmaxf(cnt[g], 1.0f);
    for (int k = threadIdx.x; k < DP1_; k += 256)
        p[k] = pooled[g * DP1_ + k] / c;
    __syncthreads();

    const int j = threadIdx.x;
    float s = __ldg(&bo1[j]);
    for (int k = 0; k < DP1_; k++)
        s = fmaf(p[k], __ldg(&Wo1[k * HID_ + j]), s);
    hid[j] = silu_f(s);
    __syncthreads();

    if (j < OUT_) {
        float o = __ldg(&bo2[j]);
        for (int k = 0; k < HID_; k++)
            o = fmaf(hid[k], __ldg(&Wo2[k * OUT_ + j]), o);
        out[g * OUT_ + j] = o;
    }
}

// ---------------- host driver ----------------
static inline dim3 gemm_grid(int M, int N) {
    return dim3((N + BN - 1) / BN, (M + BM - 1) / BM);
}

extern "C" void kernel_launch(void* const* d_in, const int* in_sizes, int n_in,
                              void* d_out, int out_size)
{
    const float* x     = (const float*)d_in[0];
    const int*   ei    = (const int*)  d_in[1];
    const int*   batch = (const int*)  d_in[2];
    const int*   sci   = (const int*)  d_in[3];
    const int*   scj   = (const int*)  d_in[4];
    const int*   sck   = (const int*)  d_in[5];
    const float* scc   = (const float*)d_in[6];
    const int*   kbr   = (const int*)  d_in[7];
    const int*   kbc   = (const int*)  d_in[8];
    const float* kbv   = (const float*)d_in[9];
    const float* Wi1   = (const float*)d_in[10];
    const float* bi1   = (const float*)d_in[11];
    const float* Wi2   = (const float*)d_in[12];
    const float* bi2   = (const float*)d_in[13];
    const float* msgW1 = (const float*)d_in[14];
    const float* msgb1 = (const float*)d_in[15];
    const float* msgW2 = (const float*)d_in[16];
    const float* msgb2 = (const float*)d_in[17];
    const float* updW1 = (const float*)d_in[18];
    const float* updb1 = (const float*)d_in[19];
    const float* updW2 = (const float*)d_in[20];
    const float* updb2 = (const float*)d_in[21];
    const float* Wo1   = (const float*)d_in[22];
    const float* bo1   = (const float*)d_in[23];
    const float* Wo2   = (const float*)d_in[24];
    const float* bo2   = (const float*)d_in[25];

    float *t1, *h, *br, *eH, *agg, *pooled, *cnt, *zbias;
    cudaGetSymbolAddress((void**)&t1,     g_t1);
    cudaGetSymbolAddress((void**)&h,      g_h);
    cudaGetSymbolAddress((void**)&br,     g_br);
    cudaGetSymbolAddress((void**)&eH,     g_eH);
    cudaGetSymbolAddress((void**)&agg,    g_agg);
    cudaGetSymbolAddress((void**)&pooled, g_pooled);
    cudaGetSymbolAddress((void**)&cnt,    g_cnt);
    cudaGetSymbolAddress((void**)&zbias,  g_zbias);

    const int* src = ei;
    const int* dst = ei + E_;

    zero_kernel<<<1, HID_>>>(zbias, HID_);
    sort_sc_kernel<<<1, 256>>>(sci, scj, sck, scc);

    // ---- input MLP: h = silu(x@Wi1+b)@Wi2+b ----
    gemm_3xbf16<<<gemm_grid(N_, HID_), 256>>>(
        x,  nullptr, x,  IN_,  Wi1, bi1, nullptr, nullptr, nullptr, t1, N_, HID_, IN_,  1);
    gemm_3xbf16<<<gemm_grid(N_, D_),   256>>>(
        t1, nullptr, t1, HID_, Wi2, bi2, nullptr, nullptr, nullptr, h,  N_, D_,   HID_, 0);

    // ---- message passing layers ----
    for (int l = 0; l < NL_; l++) {
        const float* mW1 = msgW1 + (size_t)l * D2_ * HID_;     // [496][256]
        const float* mb1 = msgb1 + (size_t)l * HID_;
        const float* mW2 = msgW2 + (size_t)l * HID_ * D_;
        const float* mb2 = msgb2 + (size_t)l * D_;
        const float* uW1 = updW1 + (size_t)l * D2_ * HID_;
        const float* ub1 = updb1 + (size_t)l * HID_;
        const float* uW2 = updW2 + (size_t)l * HID_ * D_;
        const float* ub2 = updb2 + (size_t)l * D_;

        edge_bracket_kernel<<<(E_ + EPB - 1) / EPB, 256>>>(h, ei, br);

        // node-level half of message MLP1: hw = h @ mW1[0:D] + mb1   (no act)
        gemm_3xbf16<<<gemm_grid(N_, HID_), 256>>>(
            h, nullptr, h, D_, mW1, mb1, nullptr, nullptr, nullptr, t1, N_, HID_, D_, 0);

        // edge-level half: eH = silu(br @ mW1[D:2D] + hw[src])
        gemm_3xbf16<<<gemm_grid(E_, HID_), 256>>>(
            br, nullptr, br, D_, mW1 + (size_t)D_ * HID_, zbias,
            t1, src, nullptr, eH, E_, HID_, D_, 1);

        // zero agg, then message MLP2 with fused scatter-add into agg
        {
            size_t n = (size_t)N_ * D_;
            zero_kernel<<<(unsigned)((n + 255) / 256), 256>>>(agg, n);
        }
        gemm_3xbf16<<<gemm_grid(E_, D_), 256>>>(
            eH, nullptr, eH, HID_, mW2, mb2, nullptr, nullptr, dst, agg, E_, D_, HID_, 0);

        // update MLP: A = [h | agg]
        gemm_3xbf16<<<gemm_grid(N_, HID_), 256>>>(
            h,  nullptr, agg, D_,  uW1, ub1, nullptr, nullptr, nullptr, t1, N_, HID_, D2_, 1);
        gemm_3xbf16<<<gemm_grid(N_, D_),   256>>>(
            t1, nullptr, t1,  HID_, uW2, ub2, h, nullptr, nullptr, h,  N_, D_,   HID_, 0);
    }

    // ---- killing form + pooling ----
    {
        size_t n = NG_ * DP1_;
        zero_kernel<<<(unsigned)((n + 255) / 256), 256>>>(pooled, n);
        zero_kernel<<<1, NG_>>>(cnt, NG_);
    }
    killing_pool_kernel<<<N_, 128>>>(h, batch, kbr, kbc, kbv, pooled, cnt);

    // ---- final MLP ----
    final_mlp_kernel<<<NG_, 256>>>(pooled, cnt, Wo1, bo1, Wo2, bo2, (float*)d_out);
}

// round 14
// speedup vs baseline: 1.0501x; 1.0501x over previous
#include <cuda_runtime.h>
#include <cuda_bf16.h>
#include <math.h>
#include <stdint.h>

// ---------------- problem constants ----------------
constexpr int N_   = 20000;   // nodes
constexpr int E_   = 100000;  // edges
constexpr int D_   = 248;     // Lie algebra dim
constexpr int HID_ = 256;     // MLP hidden
constexpr int IN_  = 128;     // input feature dim
constexpr int OUT_ = 16;      // output dim
constexpr int NL_  = 4;       // layers
constexpr int NNZ_ = 512;     // structure constant nnz
constexpr int NB_  = 1024;    // killing form nnz
constexpr int NG_  = 128;     // graphs
constexpr int D2_  = 2 * D_;  // 496
constexpr int DP1_ = D_ + 1;  // 249

// ---------------- scratch (device globals; allocation is forbidden) ----------------
__device__ float g_t1[(size_t)N_ * HID_];    // node hidden / hw staging
__device__ float g_h[(size_t)N_ * D_];       // node features h
__device__ float g_br[(size_t)E_ * D_];      // per-edge Lie bracket
__device__ float g_eH[(size_t)E_ * HID_];    // edge hidden
__device__ float g_agg[(size_t)N_ * D_];     // aggregated messages
__device__ float g_pooled[NG_ * DP1_];
__device__ float g_cnt[NG_];
__device__ float g_zbias[HID_];              // zero bias for split GEMM

// pair-packed weights: u32 word (p, n) = bf16x2(W[2p][n], W[2p+1][n]); [Kp/2][N] per segment
// segments: Wi1, Wi2, then per layer {mW1a, mW1b, mW2, uW1, uW2}
constexpr int NSEG = 2 + NL_ * 5;
// host-side segment sizes (words): Wi1:64*256, Wi2:128*248,
// per layer: mW1a 128*256, mW1b 128*256, mW2 128*248, uW1 256*256, uW2 128*248
constexpr size_t WP_WORDS =
    (size_t)64 * 256 + (size_t)128 * 248 +
    (size_t)NL_ * (128 * 256 + 128 * 256 + 128 * 248 + 256 * 256 + 128 * 248);
__device__ uint32_t g_wpHiW[WP_WORDS];
__device__ uint32_t g_wpLoW[WP_WORDS];

struct WSrcTab {
    const float* p[NSEG];    // source W base (row-major [K][N])
    int ko[NSEG];            // k row offset into source
    int K[NSEG];             // valid K rows
    int N[NSEG];             // columns
    long long words[NSEG];   // words in this segment (Kp/2 * N)
};

__device__ __forceinline__ float silu_f(float v) {
    return v / (1.0f + expf(-v));
}
__device__ __forceinline__ uint32_t pack_bf16(float a, float b) {
    __nv_bfloat162 t = __floats2bfloat162_rn(a, b);   // a -> low, b -> high
    return *(uint32_t*)&t;
}
__device__ __forceinline__ float bf16_round(float x) {
    return __bfloat162float(__float2bfloat16(x));
}

// ---------------- prepack all weight segments in ONE launch ----------------
__global__ __launch_bounds__(256) void prepack_all_kernel(WSrcTab tab)
{
    long long idx = (long long)blockIdx.x * 256 + threadIdx.x;
    if (idx >= (long long)WP_WORDS) return;
    int seg = 0;
    long long rem = idx;
    #pragma unroll
    for (int s = 0; s < NSEG; s++) {
        if (rem < tab.words[s]) { seg = s; break; }
        rem -= tab.words[s];
    }
    const int Nn = tab.N[seg];
    const int p  = (int)(rem / Nn);
    const int n  = (int)(rem - (long long)p * Nn);
    const int k0 = 2 * p, k1 = 2 * p + 1;
    const float* P = tab.p[seg];
    const int ko = tab.ko[seg], K = tab.K[seg];
    float v0 = (k0 < K) ? __ldg(&P[(size_t)(ko + k0) * Nn + n]) : 0.0f;
    float v1 = (k1 < K) ? __ldg(&P[(size_t)(ko + k1) * Nn + n]) : 0.0f;
    float h0 = bf16_round(v0), h1 = bf16_round(v1);
    g_wpHiW[idx] = pack_bf16(h0, h1);
    g_wpLoW[idx] = pack_bf16(v0 - h0, v1 - h1);
}

// ---------------- 3xBF16 tensor-core GEMM, double-buffered, split-K A ----------------
// C = act(A @ W + bias + res)   OR  (scatter, dstIdx != null): atomicAdd into C[dstIdx[m]]
// W is pair-packed: PHi/PLo word (p, n) covers k = 2p, 2p+1. Tiles iterate over Kp.
// A cols [0,K1) from A1 (gathered via gidx if non-null), [K1,K) from A2. K%8==0, K1%8==0.
constexpr int BM = 128, BN = 128, BK = 16;
constexpr int PA = 12;
constexpr int PW = 136;

__global__ __launch_bounds__(256, 2) void gemm_3xbf16(
    const float* __restrict__ A1, const int* __restrict__ gidx,
    const float* __restrict__ A2, int K1,
    const uint32_t* __restrict__ PHi, const uint32_t* __restrict__ PLo,
    const float* __restrict__ bias,
    const float* __restrict__ res, const int* __restrict__ resIdx,
    const int* __restrict__ dstIdx,
    float* __restrict__ C, int M, int N, int K, int Kp, int act)
{
    __shared__ uint32_t AsH[2][BM][PA];
    __shared__ uint32_t AsL[2][BM][PA];
    __shared__ uint32_t WsH[2][8][PW];
    __shared__ uint32_t WsL[2][8][PW];

    const int tid  = threadIdx.x;
    const int lane = tid & 31;
    const int wid  = tid >> 5;
    const int row0 = blockIdx.y * BM;
    const int col0 = blockIdx.x * BN;

    const int aRow = tid >> 1;            // 0..127
    const int aK8  = (tid & 1) * 8;       // 0 or 8
    const int pRow = tid >> 5;            // 0..7  (pair row within tile)
    const int wCol = lane * 4;            // 0..124

    const int K2s = K - K1;

    const int gRowA = row0 + aRow;
    const bool av = gRowA < M;
    size_t a1off = 0, a2off = 0;
    if (av) {
        int r = gidx ? __ldg(&gidx[gRowA]) : gRowA;
        a1off = (size_t)r * K1;
        a2off = (size_t)gRowA * K2s;
    }
    const int gnW = col0 + wCol;
    const bool wv = gnW < N;

    const int wm = (wid & 3) * 32;
    const int wn = (wid >> 2) * 64;
    const int grp = lane >> 2;
    const int qid = lane & 3;

    float acc[2][8][4];
    #pragma unroll
    for (int mt = 0; mt < 2; mt++)
        #pragma unroll
        for (int nt = 0; nt < 8; nt++)
            #pragma unroll
            for (int c = 0; c < 4; c++) acc[mt][nt][c] = 0.0f;

    auto loadA4 = [&](int kg) -> float4 {
        if (!av || kg >= K) return make_float4(0.f, 0.f, 0.f, 0.f);
        if (kg < K1) return *(const float4*)&A1[a1off + kg];
        return *(const float4*)&A2[a2off + (kg - K1)];
    };

    float4 aV0, aV1;
    uint4 wHi, wLo;
    auto prefetch = [&](int k0) {
        aV0 = loadA4(k0 + aK8);
        aV1 = loadA4(k0 + aK8 + 4);
        if (wv) {
            const size_t wo = (size_t)(k0 / 2 + pRow) * N + gnW;
            wHi = *(const uint4*)&PHi[wo];
            wLo = *(const uint4*)&PLo[wo];
        } else {
            wHi = make_uint4(0, 0, 0, 0);
            wLo = make_uint4(0, 0, 0, 0);
        }
    };
    auto stage = [&](int buf) {
        float h0 = bf16_round(aV0.x), h1 = bf16_round(aV0.y),
              h2 = bf16_round(aV0.z), h3 = bf16_round(aV0.w),
              h4 = bf16_round(aV1.x), h5 = bf16_round(aV1.y),
              h6 = bf16_round(aV1.z), h7 = bf16_round(aV1.w);
        uint4 hi = make_uint4(pack_bf16(h0, h1), pack_bf16(h2, h3),
                              pack_bf16(h4, h5), pack_bf16(h6, h7));
        uint4 lo = make_uint4(pack_bf16(aV0.x - h0, aV0.y - h1),
                              pack_bf16(aV0.z - h2, aV0.w - h3),
                              pack_bf16(aV1.x - h4, aV1.y - h5),
                              pack_bf16(aV1.z - h6, aV1.w - h7));
        *(uint4*)&AsH[buf][aRow][aK8 / 2] = hi;
        *(uint4*)&AsL[buf][aRow][aK8 / 2] = lo;
        *(uint4*)&WsH[buf][pRow][wCol] = wHi;   // straight copy: pre-paired words
        *(uint4*)&WsL[buf][pRow][wCol] = wLo;
    };

    const int nTiles = Kp / BK;
    prefetch(0);
    stage(0);
    if (nTiles > 1) prefetch(BK);
    __syncthreads();

    for (int t = 0; t < nTiles; t++) {
        const int buf = t & 1;
        if (t + 1 < nTiles) stage(buf ^ 1);
        if (t + 2 < nTiles) prefetch((t + 2) * BK);

        uint32_t ah[2][4], al[2][4];
        #pragma unroll
        for (int mt = 0; mt < 2; mt++) {
            const int ar = wm + 16 * mt + grp;
            ah[mt][0] = AsH[buf][ar    ][qid];
            ah[mt][1] = AsH[buf][ar + 8][qid];
            ah[mt][2] = AsH[buf][ar    ][qid + 4];
            ah[mt][3] = AsH[buf][ar + 8][qid + 4];
            al[mt][0] = AsL[buf][ar    ][qid];
            al[mt][1] = AsL[buf][ar + 8][qid];
            al[mt][2] = AsL[buf][ar    ][qid + 4];
            al[mt][3] = AsL[buf][ar + 8][qid + 4];
        }
        #pragma unroll
        for (int nt = 0; nt < 8; nt++) {
            const int bc = wn + 8 * nt + grp;
            uint32_t bh0 = WsH[buf][qid    ][bc];
            uint32_t bh1 = WsH[buf][qid + 4][bc];
            uint32_t bl0 = WsL[buf][qid    ][bc];
            uint32_t bl1 = WsL[buf][qid + 4][bc];
            #pragma unroll
            for (int mt = 0; mt < 2; mt++) {
                #define MMA_BF16(Afr, B0, B1)                                          \
                    asm volatile(                                                      \
                        "mma.sync.aligned.m16n8k16.row.col.f32.bf16.bf16.f32 "         \
                        "{%0,%1,%2,%3}, {%4,%5,%6,%7}, {%8,%9}, {%0,%1,%2,%3};"        \
                        : "+f"(acc[mt][nt][0]), "+f"(acc[mt][nt][1]),                  \
                          "+f"(acc[mt][nt][2]), "+f"(acc[mt][nt][3])                   \
                        : "r"(Afr[mt][0]), "r"(Afr[mt][1]),                            \
                          "r"(Afr[mt][2]), "r"(Afr[mt][3]),                            \
                          "r"(B0), "r"(B1))
                MMA_BF16(ah, bh0, bh1);
                MMA_BF16(al, bh0, bh1);
                MMA_BF16(ah, bl0, bl1);
                #undef MMA_BF16
            }
        }
        __syncthreads();
    }

    #pragma unroll
    for (int mt = 0; mt < 2; mt++) {
        #pragma unroll
        for (int rr = 0; rr < 2; rr++) {
            const int gm = row0 + wm + 16 * mt + grp + rr * 8;
            if (gm >= M) continue;
            int drow = 0;
            if (dstIdx) drow = __ldg(&dstIdx[gm]);
            size_t resRow = 0;
            if (res) resRow = (size_t)(resIdx ? __ldg(&resIdx[gm]) : gm) * N;
            #pragma unroll
            for (int nt = 0; nt < 8; nt++) {
                const int gn = col0 + wn + 8 * nt + qid * 2;
                if (gn >= N) continue;
                float2 bb = __ldg((const float2*)&bias[gn]);
                float v0 = acc[mt][nt][rr * 2 + 0] + bb.x;
                float v1 = acc[mt][nt][rr * 2 + 1] + bb.y;
                if (res) {
                    float2 rv = *(const float2*)&res[resRow + gn];
                    v0 += rv.x; v1 += rv.y;
                }
                if (act) { v0 = silu_f(v0); v1 = silu_f(v1); }
                if (dstIdx) {
                    atomicAdd(&C[(size_t)drow * N + gn],     v0);
                    atomicAdd(&C[(size_t)drow * N + gn + 1], v1);
                } else {
                    *(float2*)&C[(size_t)gm * N + gn] = make_float2(v0, v1);
                }
            }
        }
    }
}

// ---------------- edge gather + Lie bracket (R10 proven version) ----------------
constexpr int EPB = 8;
__global__ __launch_bounds__(256) void edge_bracket_kernel(
    const float* __restrict__ h, const int* __restrict__ ei,
    const int* __restrict__ sci, const int* __restrict__ scj,
    const int* __restrict__ sck, const float* __restrict__ scc,
    float* __restrict__ br)
{
    __shared__ int   s_i[NNZ_], s_j[NNZ_], s_k[NNZ_];
    __shared__ float s_c[NNZ_];
    __shared__ float hs[EPB][D_], hd[EPB][D_], brs[EPB][D_];

    const int tid = threadIdx.x;
    for (int t = tid; t < NNZ_; t += 256) {
        s_i[t] = __ldg(&sci[t]);
        s_j[t] = __ldg(&scj[t]);
        s_k[t] = __ldg(&sck[t]);
        s_c[t] = __ldg(&scc[t]);
    }
    __syncthreads();

    const int w = tid >> 5, lane = tid & 31;
    const int e = blockIdx.x * EPB + w;
    if (e >= E_) return;
    const int s = __ldg(&ei[e]);
    const int d = __ldg(&ei[E_ + e]);

    const float4* hsrc = (const float4*)(h + (size_t)s * D_);
    const float4* hdst = (const float4*)(h + (size_t)d * D_);
    #pragma unroll
    for (int q = lane; q < D_ / 4; q += 32) {
        ((float4*)hs[w])[q] = hsrc[q];
        ((float4*)hd[w])[q] = hdst[q];
    }
    for (int k = lane; k < D_; k += 32) brs[w][k] = 0.0f;
    __syncwarp();

    #pragma unroll
    for (int t = lane; t < NNZ_; t += 32) {
        float v = s_c[t] * hs[w][s_i[t]] * hd[w][s_j[t]];
        atomicAdd(&brs[w][s_k[t]], v);
    }
    __syncwarp();

    float4* row = (float4*)(br + (size_t)e * D_);
    #pragma unroll
    for (int q = lane; q < D_ / 4; q += 32)
        row[q] = ((const float4*)brs[w])[q];
}

__global__ void zero_kernel(float* __restrict__ p, size_t n) {
    size_t idx = (size_t)blockIdx.x * blockDim.x + threadIdx.x;
    if (idx < n) p[idx] = 0.0f;
}

// ---------------- killing form + pooling (scatter to graphs) ----------------
__global__ __launch_bounds__(128) void killing_pool_kernel(
    const float* __restrict__ h, const int* __restrict__ batch,
    const int* __restrict__ kbr, const int* __restrict__ kbc,
    const float* __restrict__ kbv,
    float* __restrict__ pooled, float* __restrict__ cnt)
{
    const int n = blockIdx.x;
    __shared__ float hrow[D_];
    __shared__ float wsum[4];
    for (int k = threadIdx.x; k < D_; k += 128)
        hrow[k] = h[(size_t)n * D_ + k];
    __syncthreads();

    float s = 0.0f;
    for (int t = threadIdx.x; t < NB_; t += 128)
        s += __ldg(&kbv[t]) * hrow[__ldg(&kbr[t])] * hrow[__ldg(&kbc[t])];
    #pragma unroll
    for (int off = 16; off > 0; off >>= 1)
        s += __shfl_down_sync(0xffffffffu, s, off);
    if ((threadIdx.x & 31) == 0) wsum[threadIdx.x >> 5] = s;
    __syncthreads();

    const int b = __ldg(&batch[n]);
    for (int k = threadIdx.x; k < D_; k += 128)
        atomicAdd(&pooled[b * DP1_ + k], hrow[k]);
    if (threadIdx.x == 0) {
        float ks = wsum[0] + wsum[1] + wsum[2] + wsum[3];
        atomicAdd(&pooled[b * DP1_ + D_], ks);
        atomicAdd(&cnt[b], 1.0f);
    }
}

// ---------------- final MLP per graph ----------------
__global__ __launch_bounds__(256) void final_mlp_kernel(
    const float* __restrict__ pooled, const float* __restrict__ cnt,
    const float* __restrict__ Wo1, const float* __restrict__ bo1,
    const float* __restrict__ Wo2, const float* __restrict__ bo2,
    float* __restrict__ out)
{
    const int g = blockIdx.x;
    __shared__ float p[DP1_];
    __shared__ float hid[HID_];
    const float c = fmaxf(cnt[g], 1.0f);
    for (int k = threadIdx.x; k < DP1_; k += 256)
        p[k] = pooled[g * DP1_ + k] / c;
    __syncthreads();

    const int j = threadIdx.x;
    float s = __ldg(&bo1[j]);
    for (int k = 0; k < DP1_; k++)
        s = fmaf(p[k], __ldg(&Wo1[k * HID_ + j]), s);
    hid[j] = silu_f(s);
    __syncthreads();

    if (j < OUT_) {
        float o = __ldg(&bo2[j]);
        for (int k = 0; k < HID_; k++)
            o = fmaf(hid[k], __ldg(&Wo2[k * OUT_ + j]), o);
        out[g * OUT_ + j] = o;
    }
}

// ---------------- host driver ----------------
static inline dim3 gemm_grid(int M, int N) {
    return dim3((N + BN - 1) / BN, (M + BM - 1) / BM);
}

extern "C" void kernel_launch(void* const* d_in, const int* in_sizes, int n_in,
                              void* d_out, int out_size)
{
    const float* x     = (const float*)d_in[0];
    const int*   ei    = (const int*)  d_in[1];
    const int*   batch = (const int*)  d_in[2];
    const int*   sci   = (const int*)  d_in[3];
    const int*   scj   = (const int*)  d_in[4];
    const int*   sck   = (const int*)  d_in[5];
    const float* scc   = (const float*)d_in[6];
    const int*   kbr   = (const int*)  d_in[7];
    const int*   kbc   = (const int*)  d_in[8];
    const float* kbv   = (const float*)d_in[9];
    const float* Wi1   = (const float*)d_in[10];
    const float* bi1   = (const float*)d_in[11];
    const float* Wi2   = (const float*)d_in[12];
    const float* bi2   = (const float*)d_in[13];
    const float* msgW1 = (const float*)d_in[14];
    const float* msgb1 = (const float*)d_in[15];
    const float* msgW2 = (const float*)d_in[16];
    const float* msgb2 = (const float*)d_in[17];
    const float* updW1 = (const float*)d_in[18];
    const float* updb1 = (const float*)d_in[19];
    const float* updW2 = (const float*)d_in[20];
    const float* updb2 = (const float*)d_in[21];
    const float* Wo1   = (const float*)d_in[22];
    const float* bo1   = (const float*)d_in[23];
    const float* Wo2   = (const float*)d_in[24];
    const float* bo2   = (const float*)d_in[25];

    float *t1, *h, *br, *eH, *agg, *pooled, *cnt, *zbias;
    uint32_t *wpHi, *wpLo;
    cudaGetSymbolAddress((void**)&t1,     g_t1);
    cudaGetSymbolAddress((void**)&h,      g_h);
    cudaGetSymbolAddress((void**)&br,     g_br);
    cudaGetSymbolAddress((void**)&eH,     g_eH);
    cudaGetSymbolAddress((void**)&agg,    g_agg);
    cudaGetSymbolAddress((void**)&pooled, g_pooled);
    cudaGetSymbolAddress((void**)&cnt,    g_cnt);
    cudaGetSymbolAddress((void**)&zbias,  g_zbias);
    cudaGetSymbolAddress((void**)&wpHi,   g_wpHiW);
    cudaGetSymbolAddress((void**)&wpLo,   g_wpLoW);

    const int* src = ei;
    const int* dst = ei + E_;

    // ---- build prepack table (22 segments) and launch once ----
    WSrcTab tab;
    long long offs[NSEG];
    {
        int s = 0;
        auto put = [&](const float* p, int ko, int K, int N, int Kp) {
            tab.p[s] = p; tab.ko[s] = ko; tab.K[s] = K; tab.N[s] = N;
            tab.words[s] = (long long)(Kp / 2) * N;
            s++;
        };
        put(Wi1, 0, IN_,  HID_, 128);
        put(Wi2, 0, HID_, D_,   256);
        for (int l = 0; l < NL_; l++) {
            const float* mW1 = msgW1 + (size_t)l * D2_ * HID_;
            const float* mW2 = msgW2 + (size_t)l * HID_ * D_;
            const float* uW1 = updW1 + (size_t)l * D2_ * HID_;
            const float* uW2 = updW2 + (size_t)l * HID_ * D_;
            put(mW1, 0,   D_,   HID_, 256);   // mW1a (node half)
            put(mW1, D_,  D_,   HID_, 256);   // mW1b (bracket half)
            put(mW2, 0,   HID_, D_,   256);
            put(uW1, 0,   D2_,  HID_, 512);
            put(uW2, 0,   HID_, D_,   256);
        }
        long long run = 0;
        for (int i = 0; i < NSEG; i++) { offs[i] = run; run += tab.words[i]; }
    }
    {
        long long nb = ((long long)WP_WORDS + 255) / 256;
        prepack_all_kernel<<<(unsigned)nb, 256>>>(tab);
    }
    zero_kernel<<<1, HID_>>>(zbias, HID_);

    const long long oWi1 = offs[0], oWi2 = offs[1];

    // ---- input MLP ----
    gemm_3xbf16<<<gemm_grid(N_, HID_), 256>>>(
        x,  nullptr, x,  IN_,  wpHi + oWi1, wpLo + oWi1, bi1,
        nullptr, nullptr, nullptr, t1, N_, HID_, IN_,  128, 1);
    gemm_3xbf16<<<gemm_grid(N_, D_),   256>>>(
        t1, nullptr, t1, HID_, wpHi + oWi2, wpLo + oWi2, bi2,
        nullptr, nullptr, nullptr, h,  N_, D_,   HID_, 256, 0);

    // ---- message passing layers ----
    for (int l = 0; l < NL_; l++) {
        const long long oA  = offs[2 + l * 5 + 0];
        const long long oB  = offs[2 + l * 5 + 1];
        const long long oM2 = offs[2 + l * 5 + 2];
        const long long oU1 = offs[2 + l * 5 + 3];
        const long long oU2 = offs[2 + l * 5 + 4];
        const float* mb1 = msgb1 + (size_t)l * HID_;
        const float* mb2 = msgb2 + (size_t)l * D_;
        const float* ub1 = updb1 + (size_t)l * HID_;
        const float* ub2 = updb2 + (size_t)l * D_;

        edge_bracket_kernel<<<(E_ + EPB - 1) / EPB, 256>>>(h, ei, sci, scj, sck, scc, br);

        // node-level half of message MLP1: hw = h @ mW1[0:D] + mb1
        gemm_3xbf16<<<gemm_grid(N_, HID_), 256>>>(
            h, nullptr, h, D_, wpHi + oA, wpLo + oA, mb1,
            nullptr, nullptr, nullptr, t1, N_, HID_, D_, 256, 0);

        // edge-level half: eH = silu(br @ mW1[D:2D] + hw[src])
        gemm_3xbf16<<<gemm_grid(E_, HID_), 256>>>(
            br, nullptr, br, D_, wpHi + oB, wpLo + oB, zbias,
            t1, src, nullptr, eH, E_, HID_, D_, 256, 1);

        // zero agg, then message MLP2 with fused scatter-add into agg
        {
            size_t n = (size_t)N_ * D_;
            zero_kernel<<<(unsigned)((n + 255) / 256), 256>>>(agg, n);
        }
        gemm_3xbf16<<<gemm_grid(E_, D_), 256>>>(
            eH, nullptr, eH, HID_, wpHi + oM2, wpLo + oM2, mb2,
            nullptr, nullptr, dst, agg, E_, D_, HID_, 256, 0);

        // update MLP: A = [h | agg]
        gemm_3xbf16<<<gemm_grid(N_, HID_), 256>>>(
            h,  nullptr, agg, D_,  wpHi + oU1, wpLo + oU1, ub1,
            nullptr, nullptr, nullptr, t1, N_, HID_, D2_, 512, 1);
        gemm_3xbf16<<<gemm_grid(N_, D_),   256>>>(
            t1, nullptr, t1,  HID_, wpHi + oU2, wpLo + oU2, ub2,
            h, nullptr, nullptr, h,  N_, D_,   HID_, 256, 0);
    }

    // ---- killing form + pooling ----
    {
        size_t n = NG_ * DP1_;
        zero_kernel<<<(unsigned)((n + 255) / 256), 256>>>(pooled, n);
        zero_kernel<<<1, NG_>>>(cnt, NG_);
    }
    killing_pool_kernel<<<N_, 128>>>(h, batch, kbr, kbc, kbv, pooled, cnt);

    // ---- final MLP ----
    final_mlp_kernel<<<NG_, 256>>>(pooled, cnt, Wo1, bo1, Wo2, bo2, (float*)d_out);
}

// round 15
// speedup vs baseline: 1.1112x; 1.0582x over previous
#include <cuda_runtime.h>
#include <cuda_bf16.h>
#include <math.h>
#include <stdint.h>

// ---------------- problem constants ----------------
constexpr int N_   = 20000;   // nodes
constexpr int E_   = 100000;  // edges
constexpr int D_   = 248;     // Lie algebra dim
constexpr int HID_ = 256;     // MLP hidden
constexpr int IN_  = 128;     // input feature dim
constexpr int OUT_ = 16;      // output dim
constexpr int NL_  = 4;       // layers
constexpr int NNZ_ = 512;     // structure constant nnz
constexpr int NB_  = 1024;    // killing form nnz
constexpr int NG_  = 128;     // graphs
constexpr int D2_  = 2 * D_;  // 496
constexpr int DP1_ = D_ + 1;  // 249

// ---------------- scratch (device globals; allocation is forbidden) ----------------
__device__ float g_t1[(size_t)N_ * HID_];    // node hidden / hw staging
__device__ float g_h[(size_t)N_ * D_];       // node features h
__device__ float g_br[(size_t)E_ * D_];      // per-edge Lie bracket
__device__ float g_eH[(size_t)E_ * HID_];    // edge hidden
__device__ float g_agg[(size_t)N_ * D_];     // aggregated messages
__device__ float g_pooled[NG_ * DP1_];
__device__ float g_cnt[NG_];
__device__ float g_zbias[HID_];              // zero bias for split GEMM

// pair-packed weights: u32 word (p, n) = bf16x2(W[2p][n], W[2p+1][n]); [Kp/2][N] per segment
constexpr int NSEG = 2 + NL_ * 5;
constexpr size_t WP_WORDS =
    (size_t)64 * 256 + (size_t)128 * 248 +
    (size_t)NL_ * (128 * 256 + 128 * 256 + 128 * 248 + 256 * 256 + 128 * 248);
__device__ uint32_t g_wpHiW[WP_WORDS];
__device__ uint32_t g_wpLoW[WP_WORDS];

struct WSrcTab {
    const float* p[NSEG];
    int ko[NSEG];
    int K[NSEG];
    int N[NSEG];
    long long words[NSEG];
};

__device__ __forceinline__ float silu_f(float v) {
    return v / (1.0f + expf(-v));
}
__device__ __forceinline__ uint32_t pack_bf16(float a, float b) {
    __nv_bfloat162 t = __floats2bfloat162_rn(a, b);
    return *(uint32_t*)&t;
}
__device__ __forceinline__ float bf16_round(float x) {
    return __bfloat162float(__float2bfloat16(x));
}

// ---------------- prepack all weight segments in ONE launch ----------------
__global__ __launch_bounds__(256) void prepack_all_kernel(WSrcTab tab)
{
    long long idx = (long long)blockIdx.x * 256 + threadIdx.x;
    if (idx >= (long long)WP_WORDS) return;
    int seg = 0;
    long long rem = idx;
    #pragma unroll
    for (int s = 0; s < NSEG; s++) {
        if (rem < tab.words[s]) { seg = s; break; }
        rem -= tab.words[s];
    }
    const int Nn = tab.N[seg];
    const int p  = (int)(rem / Nn);
    const int n  = (int)(rem - (long long)p * Nn);
    const int k0 = 2 * p, k1 = 2 * p + 1;
    const float* P = tab.p[seg];
    const int ko = tab.ko[seg], K = tab.K[seg];
    float v0 = (k0 < K) ? __ldg(&P[(size_t)(ko + k0) * Nn + n]) : 0.0f;
    float v1 = (k1 < K) ? __ldg(&P[(size_t)(ko + k1) * Nn + n]) : 0.0f;
    float h0 = bf16_round(v0), h1 = bf16_round(v1);
    g_wpHiW[idx] = pack_bf16(h0, h1);
    g_wpLoW[idx] = pack_bf16(v0 - h0, v1 - h1);
}

// ---------------- 3xBF16 tensor-core GEMM (R14 proven) ----------------
constexpr int BM = 128, BN = 128, BK = 16;
constexpr int PA = 12;
constexpr int PW = 136;

__global__ __launch_bounds__(256, 2) void gemm_3xbf16(
    const float* __restrict__ A1, const int* __restrict__ gidx,
    const float* __restrict__ A2, int K1,
    const uint32_t* __restrict__ PHi, const uint32_t* __restrict__ PLo,
    const float* __restrict__ bias,
    const float* __restrict__ res, const int* __restrict__ resIdx,
    const int* __restrict__ dstIdx,
    float* __restrict__ C, int M, int N, int K, int Kp, int act)
{
    __shared__ uint32_t AsH[2][BM][PA];
    __shared__ uint32_t AsL[2][BM][PA];
    __shared__ uint32_t WsH[2][8][PW];
    __shared__ uint32_t WsL[2][8][PW];

    const int tid  = threadIdx.x;
    const int lane = tid & 31;
    const int wid  = tid >> 5;
    const int row0 = blockIdx.y * BM;
    const int col0 = blockIdx.x * BN;

    const int aRow = tid >> 1;
    const int aK8  = (tid & 1) * 8;
    const int pRow = tid >> 5;
    const int wCol = lane * 4;

    const int K2s = K - K1;

    const int gRowA = row0 + aRow;
    const bool av = gRowA < M;
    size_t a1off = 0, a2off = 0;
    if (av) {
        int r = gidx ? __ldg(&gidx[gRowA]) : gRowA;
        a1off = (size_t)r * K1;
        a2off = (size_t)gRowA * K2s;
    }
    const int gnW = col0 + wCol;
    const bool wv = gnW < N;

    const int wm = (wid & 3) * 32;
    const int wn = (wid >> 2) * 64;
    const int grp = lane >> 2;
    const int qid = lane & 3;

    float acc[2][8][4];
    #pragma unroll
    for (int mt = 0; mt < 2; mt++)
        #pragma unroll
        for (int nt = 0; nt < 8; nt++)
            #pragma unroll
            for (int c = 0; c < 4; c++) acc[mt][nt][c] = 0.0f;

    auto loadA4 = [&](int kg) -> float4 {
        if (!av || kg >= K) return make_float4(0.f, 0.f, 0.f, 0.f);
        if (kg < K1) return *(const float4*)&A1[a1off + kg];
        return *(const float4*)&A2[a2off + (kg - K1)];
    };

    float4 aV0, aV1;
    uint4 wHi, wLo;
    auto prefetch = [&](int k0) {
        aV0 = loadA4(k0 + aK8);
        aV1 = loadA4(k0 + aK8 + 4);
        if (wv) {
            const size_t wo = (size_t)(k0 / 2 + pRow) * N + gnW;
            wHi = *(const uint4*)&PHi[wo];
            wLo = *(const uint4*)&PLo[wo];
        } else {
            wHi = make_uint4(0, 0, 0, 0);
            wLo = make_uint4(0, 0, 0, 0);
        }
    };
    auto stage = [&](int buf) {
        float h0 = bf16_round(aV0.x), h1 = bf16_round(aV0.y),
              h2 = bf16_round(aV0.z), h3 = bf16_round(aV0.w),
              h4 = bf16_round(aV1.x), h5 = bf16_round(aV1.y),
              h6 = bf16_round(aV1.z), h7 = bf16_round(aV1.w);
        uint4 hi = make_uint4(pack_bf16(h0, h1), pack_bf16(h2, h3),
                              pack_bf16(h4, h5), pack_bf16(h6, h7));
        uint4 lo = make_uint4(pack_bf16(aV0.x - h0, aV0.y - h1),
                              pack_bf16(aV0.z - h2, aV0.w - h3),
                              pack_bf16(aV1.x - h4, aV1.y - h5),
                              pack_bf16(aV1.z - h6, aV1.w - h7));
        *(uint4*)&AsH[buf][aRow][aK8 / 2] = hi;
        *(uint4*)&AsL[buf][aRow][aK8 / 2] = lo;
        *(uint4*)&WsH[buf][pRow][wCol] = wHi;
        *(uint4*)&WsL[buf][pRow][wCol] = wLo;
    };

    const int nTiles = Kp / BK;
    prefetch(0);
    stage(0);
    if (nTiles > 1) prefetch(BK);
    __syncthreads();

    for (int t = 0; t < nTiles; t++) {
        const int buf = t & 1;
        if (t + 1 < nTiles) stage(buf ^ 1);
        if (t + 2 < nTiles) prefetch((t + 2) * BK);

        uint32_t ah[2][4], al[2][4];
        #pragma unroll
        for (int mt = 0; mt < 2; mt++) {
            const int ar = wm + 16 * mt + grp;
            ah[mt][0] = AsH[buf][ar    ][qid];
            ah[mt][1] = AsH[buf][ar + 8][qid];
            ah[mt][2] = AsH[buf][ar    ][qid + 4];
            ah[mt][3] = AsH[buf][ar + 8][qid + 4];
            al[mt][0] = AsL[buf][ar    ][qid];
            al[mt][1] = AsL[buf][ar + 8][qid];
            al[mt][2] = AsL[buf][ar    ][qid + 4];
            al[mt][3] = AsL[buf][ar + 8][qid + 4];
        }
        #pragma unroll
        for (int nt = 0; nt < 8; nt++) {
            const int bc = wn + 8 * nt + grp;
            uint32_t bh0 = WsH[buf][qid    ][bc];
            uint32_t bh1 = WsH[buf][qid + 4][bc];
            uint32_t bl0 = WsL[buf][qid    ][bc];
            uint32_t bl1 = WsL[buf][qid + 4][bc];
            #pragma unroll
            for (int mt = 0; mt < 2; mt++) {
                #define MMA_BF16(Afr, B0, B1)                                          \
                    asm volatile(                                                      \
                        "mma.sync.aligned.m16n8k16.row.col.f32.bf16.bf16.f32 "         \
                        "{%0,%1,%2,%3}, {%4,%5,%6,%7}, {%8,%9}, {%0,%1,%2,%3};"        \
                        : "+f"(acc[mt][nt][0]), "+f"(acc[mt][nt][1]),                  \
                          "+f"(acc[mt][nt][2]), "+f"(acc[mt][nt][3])                   \
                        : "r"(Afr[mt][0]), "r"(Afr[mt][1]),                            \
                          "r"(Afr[mt][2]), "r"(Afr[mt][3]),                            \
                          "r"(B0), "r"(B1))
                MMA_BF16(ah, bh0, bh1);
                MMA_BF16(al, bh0, bh1);
                MMA_BF16(ah, bl0, bl1);
                #undef MMA_BF16
            }
        }
        __syncthreads();
    }

    #pragma unroll
    for (int mt = 0; mt < 2; mt++) {
        #pragma unroll
        for (int rr = 0; rr < 2; rr++) {
            const int gm = row0 + wm + 16 * mt + grp + rr * 8;
            if (gm >= M) continue;
            int drow = 0;
            if (dstIdx) drow = __ldg(&dstIdx[gm]);
            size_t resRow = 0;
            if (res) resRow = (size_t)(resIdx ? __ldg(&resIdx[gm]) : gm) * N;
            #pragma unroll
            for (int nt = 0; nt < 8; nt++) {
                const int gn = col0 + wn + 8 * nt + qid * 2;
                if (gn >= N) continue;
                float2 bb = __ldg((const float2*)&bias[gn]);
                float v0 = acc[mt][nt][rr * 2 + 0] + bb.x;
                float v1 = acc[mt][nt][rr * 2 + 1] + bb.y;
                if (res) {
                    float2 rv = *(const float2*)&res[resRow + gn];
                    v0 += rv.x; v1 += rv.y;
                }
                if (act) { v0 = silu_f(v0); v1 = silu_f(v1); }
                if (dstIdx) {
                    atomicAdd(&C[(size_t)drow * N + gn],     v0);
                    atomicAdd(&C[(size_t)drow * N + gn + 1], v1);
                } else {
                    *(float2*)&C[(size_t)gm * N + gn] = make_float2(v0, v1);
                }
            }
        }
    }
}

// ---------------- edge bracket, transposed-edge layout (conflict-free) ----------------
// Block handles TEB=32 edges; smem tiles hsT/hdT/brT are [D][33] (stride-33 pad).
// In the nnz loop, lane = edge: hsT[i][lane] has bank (i+lane)%32 -> conflict-free;
// COO reads are warp-broadcast; brT atomics are spread-address.
constexpr int TEB = 32;
constexpr int BRS = 33;                           // padded edge stride
constexpr uint32_t BR_TILE = D_ * BRS;            // 8184 floats
constexpr uint32_t BR_SMEM = (3 * BR_TILE + 4 * NNZ_) * 4;   // 106400 bytes

__global__ __launch_bounds__(256) void edge_bracket_T(
    const float* __restrict__ h, const int* __restrict__ ei,
    const int* __restrict__ sci, const int* __restrict__ scj,
    const int* __restrict__ sck, const float* __restrict__ scc,
    float* __restrict__ br)
{
    extern __shared__ float sm[];
    float* hsT = sm;
    float* hdT = sm + BR_TILE;
    float* brT = sm + 2 * BR_TILE;
    int*   s_i = (int*)(sm + 3 * BR_TILE);
    int*   s_j = s_i + NNZ_;
    int*   s_k = s_j + NNZ_;
    float* s_c = (float*)(s_k + NNZ_);

    const int tid = threadIdx.x;
    for (int t = tid; t < NNZ_; t += 256) {
        s_i[t] = __ldg(&sci[t]);
        s_j[t] = __ldg(&scj[t]);
        s_k[t] = __ldg(&sck[t]);
        s_c[t] = __ldg(&scc[t]);
    }
    for (int q = tid; q < (int)BR_TILE; q += 256) brT[q] = 0.0f;

    // ---- load 32 edges' h rows, transposed (coalesced LDG, conflict-free STS) ----
    const int e   = tid >> 3;          // 0..31
    const int sub = tid & 7;           // 0..7
    const int eg  = blockIdx.x * TEB + e;   // E_ % TEB == 0, no guard needed
    const int sn  = __ldg(&ei[eg]);
    const int dn  = __ldg(&ei[E_ + eg]);
    const float4* hs4 = (const float4*)(h + (size_t)sn * D_);
    const float4* hd4 = (const float4*)(h + (size_t)dn * D_);
    #pragma unroll
    for (int j = 0; j < 8; j++) {
        const int q4 = sub + j * 8;
        if (q4 < D_ / 4) {
            float4 a = hs4[q4];
            float4 b = hd4[q4];
            const int d = q4 * 4;
            hsT[(d + 0) * BRS + e] = a.x;
            hsT[(d + 1) * BRS + e] = a.y;
            hsT[(d + 2) * BRS + e] = a.z;
            hsT[(d + 3) * BRS + e] = a.w;
            hdT[(d + 0) * BRS + e] = b.x;
            hdT[(d + 1) * BRS + e] = b.y;
            hdT[(d + 2) * BRS + e] = b.z;
            hdT[(d + 3) * BRS + e] = b.w;
        }
    }
    __syncthreads();

    // ---- nnz loop: warp w covers t in [w*64, w*64+64), lane = edge ----
    const int w = tid >> 5, lane = tid & 31;
    for (int t = w * 64; t < w * 64 + 64; t++) {
        const float v = s_c[t] * hsT[s_i[t] * BRS + lane] * hdT[s_j[t] * BRS + lane];
        atomicAdd(&brT[s_k[t] * BRS + lane], v);
    }
    __syncthreads();

    // ---- writeback (conflict-free LDS, coalesced STG) ----
    float4* brow = (float4*)(br + (size_t)eg * D_);
    #pragma unroll
    for (int j = 0; j < 8; j++) {
        const int q4 = sub + j * 8;
        if (q4 < D_ / 4) {
            const int d = q4 * 4;
            brow[q4] = make_float4(brT[(d + 0) * BRS + e], brT[(d + 1) * BRS + e],
                                   brT[(d + 2) * BRS + e], brT[(d + 3) * BRS + e]);
        }
    }
}

__global__ void zero_kernel(float* __restrict__ p, size_t n) {
    size_t idx = (size_t)blockIdx.x * blockDim.x + threadIdx.x;
    if (idx < n) p[idx] = 0.0f;
}

// ---------------- killing form + pooling (scatter to graphs) ----------------
__global__ __launch_bounds__(128) void killing_pool_kernel(
    const float* __restrict__ h, const int* __restrict__ batch,
    const int* __restrict__ kbr, const int* __restrict__ kbc,
    const float* __restrict__ kbv,
    float* __restrict__ pooled, float* __restrict__ cnt)
{
    const int n = blockIdx.x;
    __shared__ float hrow[D_];
    __shared__ float wsum[4];
    for (int k = threadIdx.x; k < D_; k += 128)
        hrow[k] = h[(size_t)n * D_ + k];
    __syncthreads();

    float s = 0.0f;
    for (int t = threadIdx.x; t < NB_; t += 128)
        s += __ldg(&kbv[t]) * hrow[__ldg(&kbr[t])] * hrow[__ldg(&kbc[t])];
    #pragma unroll
    for (int off = 16; off > 0; off >>= 1)
        s += __shfl_down_sync(0xffffffffu, s, off);
    if ((threadIdx.x & 31) == 0) wsum[threadIdx.x >> 5] = s;
    __syncthreads();

    const int b = __ldg(&batch[n]);
    for (int k = threadIdx.x; k < D_; k += 128)
        atomicAdd(&pooled[b * DP1_ + k], hrow[k]);
    if (threadIdx.x == 0) {
        float ks = wsum[0] + wsum[1] + wsum[2] + wsum[3];
        atomicAdd(&pooled[b * DP1_ + D_], ks);
        atomicAdd(&cnt[b], 1.0f);
    }
}

// ---------------- final MLP per graph ----------------
__global__ __launch_bounds__(256) void final_mlp_kernel(
    const float* __restrict__ pooled, const float* __restrict__ cnt,
    const float* __restrict__ Wo1, const float* __restrict__ bo1,
    const float* __restrict__ Wo2, const float* __restrict__ bo2,
    float* __restrict__ out)
{
    const int g = blockIdx.x;
    __shared__ float p[DP1_];
    __shared__ float hid[HID_];
    const float c = fmaxf(cnt[g], 1.0f);
    for (int k = threadIdx.x; k < DP1_; k += 256)
        p[k] = pooled[g * DP1_ + k] / c;
    __syncthreads();

    const int j = threadIdx.x;
    float s = __ldg(&bo1[j]);
    for (int k = 0; k < DP1_; k++)
        s = fmaf(p[k], __ldg(&Wo1[k * HID_ + j]), s);
    hid[j] = silu_f(s);
    __syncthreads();

    if (j < OUT_) {
        float o = __ldg(&bo2[j]);
        for (int k = 0; k < HID_; k++)
            o = fmaf(hid[k], __ldg(&Wo2[k * OUT_ + j]), o);
        out[g * OUT_ + j] = o;
    }
}

// ---------------- host driver ----------------
static inline dim3 gemm_grid(int M, int N) {
    return dim3((N + BN - 1) / BN, (M + BM - 1) / BM);
}

extern "C" void kernel_launch(void* const* d_in, const int* in_sizes, int n_in,
                              void* d_out, int out_size)
{
    const float* x     = (const float*)d_in[0];
    const int*   ei    = (const int*)  d_in[1];
    const int*   batch = (const int*)  d_in[2];
    const int*   sci   = (const int*)  d_in[3];
    const int*   scj   = (const int*)  d_in[4];
    const int*   sck   = (const int*)  d_in[5];
    const float* scc   = (const float*)d_in[6];
    const int*   kbr   = (const int*)  d_in[7];
    const int*   kbc   = (const int*)  d_in[8];
    const float* kbv   = (const float*)d_in[9];
    const float* Wi1   = (const float*)d_in[10];
    const float* bi1   = (const float*)d_in[11];
    const float* Wi2   = (const float*)d_in[12];
    const float* bi2   = (const float*)d_in[13];
    const float* msgW1 = (const float*)d_in[14];
    const float* msgb1 = (const float*)d_in[15];
    const float* msgW2 = (const float*)d_in[16];
    const float* msgb2 = (const float*)d_in[17];
    const float* updW1 = (const float*)d_in[18];
    const float* updb1 = (const float*)d_in[19];
    const float* updW2 = (const float*)d_in[20];
    const float* updb2 = (const float*)d_in[21];
    const float* Wo1   = (const float*)d_in[22];
    const float* bo1   = (const float*)d_in[23];
    const float* Wo2   = (const float*)d_in[24];
    const float* bo2   = (const float*)d_in[25];

    float *t1, *h, *br, *eH, *agg, *pooled, *cnt, *zbias;
    uint32_t *wpHi, *wpLo;
    cudaGetSymbolAddress((void**)&t1,     g_t1);
    cudaGetSymbolAddress((void**)&h,      g_h);
    cudaGetSymbolAddress((void**)&br,     g_br);
    cudaGetSymbolAddress((void**)&eH,     g_eH);
    cudaGetSymbolAddress((void**)&agg,    g_agg);
    cudaGetSymbolAddress((void**)&pooled, g_pooled);
    cudaGetSymbolAddress((void**)&cnt,    g_cnt);
    cudaGetSymbolAddress((void**)&zbias,  g_zbias);
    cudaGetSymbolAddress((void**)&wpHi,   g_wpHiW);
    cudaGetSymbolAddress((void**)&wpLo,   g_wpLoW);

    cudaFuncSetAttribute(edge_bracket_T,
                         cudaFuncAttributeMaxDynamicSharedMemorySize, (int)BR_SMEM);

    const int* src = ei;
    const int* dst = ei + E_;

    // ---- build prepack table (22 segments) and launch once ----
    WSrcTab tab;
    long long offs[NSEG];
    {
        int s = 0;
        auto put = [&](const float* p, int ko, int K, int N, int Kp) {
            tab.p[s] = p; tab.ko[s] = ko; tab.K[s] = K; tab.N[s] = N;
            tab.words[s] = (long long)(Kp / 2) * N;
            s++;
        };
        put(Wi1, 0, IN_,  HID_, 128);
        put(Wi2, 0, HID_, D_,   256);
        for (int l = 0; l < NL_; l++) {
            const float* mW1 = msgW1 + (size_t)l * D2_ * HID_;
            const float* mW2 = msgW2 + (size_t)l * HID_ * D_;
            const float* uW1 = updW1 + (size_t)l * D2_ * HID_;
            const float* uW2 = updW2 + (size_t)l * HID_ * D_;
            put(mW1, 0,   D_,   HID_, 256);   // mW1a (node half)
            put(mW1, D_,  D_,   HID_, 256);   // mW1b (bracket half)
            put(mW2, 0,   HID_, D_,   256);
            put(uW1, 0,   D2_,  HID_, 512);
            put(uW2, 0,   HID_, D_,   256);
        }
        long long run = 0;
        for (int i = 0; i < NSEG; i++) { offs[i] = run; run += tab.words[i]; }
    }
    {
        long long nb = ((long long)WP_WORDS + 255) / 256;
        prepack_all_kernel<<<(unsigned)nb, 256>>>(tab);
    }
    zero_kernel<<<1, HID_>>>(zbias, HID_);

    const long long oWi1 = offs[0], oWi2 = offs[1];

    // ---- input MLP ----
    gemm_3xbf16<<<gemm_grid(N_, HID_), 256>>>(
        x,  nullptr, x,  IN_,  wpHi + oWi1, wpLo + oWi1, bi1,
        nullptr, nullptr, nullptr, t1, N_, HID_, IN_,  128, 1);
    gemm_3xbf16<<<gemm_grid(N_, D_),   256>>>(
        t1, nullptr, t1, HID_, wpHi + oWi2, wpLo + oWi2, bi2,
        nullptr, nullptr, nullptr, h,  N_, D_,   HID_, 256, 0);

    // ---- message passing layers ----
    for (int l = 0; l < NL_; l++) {
        const long long oA  = offs[2 + l * 5 + 0];
        const long long oB  = offs[2 + l * 5 + 1];
        const long long oM2 = offs[2 + l * 5 + 2];
        const long long oU1 = offs[2 + l * 5 + 3];
        const long long oU2 = offs[2 + l * 5 + 4];
        const float* mb1 = msgb1 + (size_t)l * HID_;
        const float* mb2 = msgb2 + (size_t)l * D_;
        const float* ub1 = updb1 + (size_t)l * HID_;
        const float* ub2 = updb2 + (size_t)l * D_;

        edge_bracket_T<<<E_ / TEB, 256, BR_SMEM>>>(h, ei, sci, scj, sck, scc, br);

        // node-level half of message MLP1: hw = h @ mW1[0:D] + mb1
        gemm_3xbf16<<<gemm_grid(N_, HID_), 256>>>(
            h, nullptr, h, D_, wpHi + oA, wpLo + oA, mb1,
            nullptr, nullptr, nullptr, t1, N_, HID_, D_, 256, 0);

        // edge-level half: eH = silu(br @ mW1[D:2D] + hw[src])
        gemm_3xbf16<<<gemm_grid(E_, HID_), 256>>>(
            br, nullptr, br, D_, wpHi + oB, wpLo + oB, zbias,
            t1, src, nullptr, eH, E_, HID_, D_, 256, 1);

        // zero agg, then message MLP2 with fused scatter-add into agg
        {
            size_t n = (size_t)N_ * D_;
            zero_kernel<<<(unsigned)((n + 255) / 256), 256>>>(agg, n);
        }
        gemm_3xbf16<<<gemm_grid(E_, D_), 256>>>(
            eH, nullptr, eH, HID_, wpHi + oM2, wpLo + oM2, mb2,
            nullptr, nullptr, dst, agg, E_, D_, HID_, 256, 0);

        // update MLP: A = [h | agg]
        gemm_3xbf16<<<gemm_grid(N_, HID_), 256>>>(
            h,  nullptr, agg, D_,  wpHi + oU1, wpLo + oU1, ub1,
            nullptr, nullptr, nullptr, t1, N_, HID_, D2_, 512, 1);
        gemm_3xbf16<<<gemm_grid(N_, D_),   256>>>(
            t1, nullptr, t1,  HID_, wpHi + oU2, wpLo + oU2, ub2,
            h, nullptr, nullptr, h,  N_, D_,   HID_, 256, 0);
    }

    // ---- killing form + pooling ----
    {
        size_t n = NG_ * DP1_;
        zero_kernel<<<(unsigned)((n + 255) / 256), 256>>>(pooled, n);
        zero_kernel<<<1, NG_>>>(cnt, NG_);
    }
    killing_pool_kernel<<<N_, 128>>>(h, batch, kbr, kbc, kbv, pooled, cnt);

    // ---- final MLP ----
    final_mlp_kernel<<<NG_, 256>>>(pooled, cnt, Wo1, bo1, Wo2, bo2, (float*)d_out);
}

// round 16
// speedup vs baseline: 1.1502x; 1.0351x over previous
#include <cuda_runtime.h>
#include <cuda_bf16.h>
#include <math.h>
#include <stdint.h>

// ---------------- problem constants ----------------
constexpr int N_   = 20000;   // nodes
constexpr int E_   = 100000;  // edges
constexpr int D_   = 248;     // Lie algebra dim
constexpr int HID_ = 256;     // MLP hidden
constexpr int IN_  = 128;     // input feature dim
constexpr int OUT_ = 16;      // output dim
constexpr int NL_  = 4;       // layers
constexpr int NNZ_ = 512;     // structure constant nnz
constexpr int NB_  = 1024;    // killing form nnz
constexpr int NG_  = 128;     // graphs
constexpr int D2_  = 2 * D_;  // 496
constexpr int DP1_ = D_ + 1;  // 249

// ---------------- scratch (device globals; allocation is forbidden) ----------------
__device__ float g_t1[(size_t)N_ * HID_];    // node hidden / hw staging
__device__ float g_h[(size_t)N_ * D_];       // node features h
__device__ float g_br[(size_t)E_ * D_];      // per-edge Lie bracket
__device__ float g_eH[(size_t)E_ * HID_];    // edge hidden
__device__ float g_agg[(size_t)N_ * D_];     // aggregated messages
__device__ float g_pooled[NG_ * DP1_];
__device__ float g_cnt[NG_];
__device__ float g_zbias[HID_];              // zero bias for split GEMM

// pair-packed weights: u32 word (p, n) = bf16x2(W[2p][n], W[2p+1][n]); [Kp/2][N] per segment
constexpr int NSEG = 2 + NL_ * 5;
constexpr size_t WP_WORDS =
    (size_t)64 * 256 + (size_t)128 * 248 +
    (size_t)NL_ * (128 * 256 + 128 * 256 + 128 * 248 + 256 * 256 + 128 * 248);
__device__ uint32_t g_wpHiW[WP_WORDS];
__device__ uint32_t g_wpLoW[WP_WORDS];

struct WSrcTab {
    const float* p[NSEG];
    int ko[NSEG];
    int K[NSEG];
    int N[NSEG];
    long long words[NSEG];
};

__device__ __forceinline__ float silu_f(float v) {
    return v / (1.0f + expf(-v));
}
__device__ __forceinline__ uint32_t pack_bf16(float a, float b) {
    __nv_bfloat162 t = __floats2bfloat162_rn(a, b);
    return *(uint32_t*)&t;
}
__device__ __forceinline__ float bf16_round(float x) {
    return __bfloat162float(__float2bfloat16(x));
}

// ---------------- prepack all weight segments in ONE launch ----------------
__global__ __launch_bounds__(256) void prepack_all_kernel(WSrcTab tab)
{
    long long idx = (long long)blockIdx.x * 256 + threadIdx.x;
    if (idx >= (long long)WP_WORDS) return;
    int seg = 0;
    long long rem = idx;
    #pragma unroll
    for (int s = 0; s < NSEG; s++) {
        if (rem < tab.words[s]) { seg = s; break; }
        rem -= tab.words[s];
    }
    const int Nn = tab.N[seg];
    const int p  = (int)(rem / Nn);
    const int n  = (int)(rem - (long long)p * Nn);
    const int k0 = 2 * p, k1 = 2 * p + 1;
    const float* P = tab.p[seg];
    const int ko = tab.ko[seg], K = tab.K[seg];
    float v0 = (k0 < K) ? __ldg(&P[(size_t)(ko + k0) * Nn + n]) : 0.0f;
    float v1 = (k1 < K) ? __ldg(&P[(size_t)(ko + k1) * Nn + n]) : 0.0f;
    float h0 = bf16_round(v0), h1 = bf16_round(v1);
    g_wpHiW[idx] = pack_bf16(h0, h1);
    g_wpLoW[idx] = pack_bf16(v0 - h0, v1 - h1);
}

// ---------------- 3xBF16 tensor-core GEMM (R14/R15 proven) ----------------
constexpr int BM = 128, BN = 128, BK = 16;
constexpr int PA = 12;
constexpr int PW = 136;

__global__ __launch_bounds__(256, 2) void gemm_3xbf16(
    const float* __restrict__ A1, const int* __restrict__ gidx,
    const float* __restrict__ A2, int K1,
    const uint32_t* __restrict__ PHi, const uint32_t* __restrict__ PLo,
    const float* __restrict__ bias,
    const float* __restrict__ res, const int* __restrict__ resIdx,
    const int* __restrict__ dstIdx,
    float* __restrict__ C, int M, int N, int K, int Kp, int act)
{
    __shared__ uint32_t AsH[2][BM][PA];
    __shared__ uint32_t AsL[2][BM][PA];
    __shared__ uint32_t WsH[2][8][PW];
    __shared__ uint32_t WsL[2][8][PW];

    const int tid  = threadIdx.x;
    const int lane = tid & 31;
    const int wid  = tid >> 5;
    const int row0 = blockIdx.y * BM;
    const int col0 = blockIdx.x * BN;

    const int aRow = tid >> 1;
    const int aK8  = (tid & 1) * 8;
    const int pRow = tid >> 5;
    const int wCol = lane * 4;

    const int K2s = K - K1;

    const int gRowA = row0 + aRow;
    const bool av = gRowA < M;
    size_t a1off = 0, a2off = 0;
    if (av) {
        int r = gidx ? __ldg(&gidx[gRowA]) : gRowA;
        a1off = (size_t)r * K1;
        a2off = (size_t)gRowA * K2s;
    }
    const int gnW = col0 + wCol;
    const bool wv = gnW < N;

    const int wm = (wid & 3) * 32;
    const int wn = (wid >> 2) * 64;
    const int grp = lane >> 2;
    const int qid = lane & 3;

    float acc[2][8][4];
    #pragma unroll
    for (int mt = 0; mt < 2; mt++)
        #pragma unroll
        for (int nt = 0; nt < 8; nt++)
            #pragma unroll
            for (int c = 0; c < 4; c++) acc[mt][nt][c] = 0.0f;

    auto loadA4 = [&](int kg) -> float4 {
        if (!av || kg >= K) return make_float4(0.f, 0.f, 0.f, 0.f);
        if (kg < K1) return *(const float4*)&A1[a1off + kg];
        return *(const float4*)&A2[a2off + (kg - K1)];
    };

    float4 aV0, aV1;
    uint4 wHi, wLo;
    auto prefetch = [&](int k0) {
        aV0 = loadA4(k0 + aK8);
        aV1 = loadA4(k0 + aK8 + 4);
        if (wv) {
            const size_t wo = (size_t)(k0 / 2 + pRow) * N + gnW;
            wHi = *(const uint4*)&PHi[wo];
            wLo = *(const uint4*)&PLo[wo];
        } else {
            wHi = make_uint4(0, 0, 0, 0);
            wLo = make_uint4(0, 0, 0, 0);
        }
    };
    auto stage = [&](int buf) {
        float h0 = bf16_round(aV0.x), h1 = bf16_round(aV0.y),
              h2 = bf16_round(aV0.z), h3 = bf16_round(aV0.w),
              h4 = bf16_round(aV1.x), h5 = bf16_round(aV1.y),
              h6 = bf16_round(aV1.z), h7 = bf16_round(aV1.w);
        uint4 hi = make_uint4(pack_bf16(h0, h1), pack_bf16(h2, h3),
                              pack_bf16(h4, h5), pack_bf16(h6, h7));
        uint4 lo = make_uint4(pack_bf16(aV0.x - h0, aV0.y - h1),
                              pack_bf16(aV0.z - h2, aV0.w - h3),
                              pack_bf16(aV1.x - h4, aV1.y - h5),
                              pack_bf16(aV1.z - h6, aV1.w - h7));
        *(uint4*)&AsH[buf][aRow][aK8 / 2] = hi;
        *(uint4*)&AsL[buf][aRow][aK8 / 2] = lo;
        *(uint4*)&WsH[buf][pRow][wCol] = wHi;
        *(uint4*)&WsL[buf][pRow][wCol] = wLo;
    };

    const int nTiles = Kp / BK;
    prefetch(0);
    stage(0);
    if (nTiles > 1) prefetch(BK);
    __syncthreads();

    for (int t = 0; t < nTiles; t++) {
        const int buf = t & 1;
        if (t + 1 < nTiles) stage(buf ^ 1);
        if (t + 2 < nTiles) prefetch((t + 2) * BK);

        uint32_t ah[2][4], al[2][4];
        #pragma unroll
        for (int mt = 0; mt < 2; mt++) {
            const int ar = wm + 16 * mt + grp;
            ah[mt][0] = AsH[buf][ar    ][qid];
            ah[mt][1] = AsH[buf][ar + 8][qid];
            ah[mt][2] = AsH[buf][ar    ][qid + 4];
            ah[mt][3] = AsH[buf][ar + 8][qid + 4];
            al[mt][0] = AsL[buf][ar    ][qid];
            al[mt][1] = AsL[buf][ar + 8][qid];
            al[mt][2] = AsL[buf][ar    ][qid + 4];
            al[mt][3] = AsL[buf][ar + 8][qid + 4];
        }
        #pragma unroll
        for (int nt = 0; nt < 8; nt++) {
            const int bc = wn + 8 * nt + grp;
            uint32_t bh0 = WsH[buf][qid    ][bc];
            uint32_t bh1 = WsH[buf][qid + 4][bc];
            uint32_t bl0 = WsL[buf][qid    ][bc];
            uint32_t bl1 = WsL[buf][qid + 4][bc];
            #pragma unroll
            for (int mt = 0; mt < 2; mt++) {
                #define MMA_BF16(Afr, B0, B1)                                          \
                    asm volatile(                                                      \
                        "mma.sync.aligned.m16n8k16.row.col.f32.bf16.bf16.f32 "         \
                        "{%0,%1,%2,%3}, {%4,%5,%6,%7}, {%8,%9}, {%0,%1,%2,%3};"        \
                        : "+f"(acc[mt][nt][0]), "+f"(acc[mt][nt][1]),                  \
                          "+f"(acc[mt][nt][2]), "+f"(acc[mt][nt][3])                   \
                        : "r"(Afr[mt][0]), "r"(Afr[mt][1]),                            \
                          "r"(Afr[mt][2]), "r"(Afr[mt][3]),                            \
                          "r"(B0), "r"(B1))
                MMA_BF16(ah, bh0, bh1);
                MMA_BF16(al, bh0, bh1);
                MMA_BF16(ah, bl0, bl1);
                #undef MMA_BF16
            }
        }
        __syncthreads();
    }

    #pragma unroll
    for (int mt = 0; mt < 2; mt++) {
        #pragma unroll
        for (int rr = 0; rr < 2; rr++) {
            const int gm = row0 + wm + 16 * mt + grp + rr * 8;
            if (gm >= M) continue;
            int drow = 0;
            if (dstIdx) drow = __ldg(&dstIdx[gm]);
            size_t resRow = 0;
            if (res) resRow = (size_t)(resIdx ? __ldg(&resIdx[gm]) : gm) * N;
            #pragma unroll
            for (int nt = 0; nt < 8; nt++) {
                const int gn = col0 + wn + 8 * nt + qid * 2;
                if (gn >= N) continue;
                float2 bb = __ldg((const float2*)&bias[gn]);
                float v0 = acc[mt][nt][rr * 2 + 0] + bb.x;
                float v1 = acc[mt][nt][rr * 2 + 1] + bb.y;
                if (res) {
                    float2 rv = *(const float2*)&res[resRow + gn];
                    v0 += rv.x; v1 += rv.y;
                }
                if (act) { v0 = silu_f(v0); v1 = silu_f(v1); }
                if (dstIdx) {
                    atomicAdd(&C[(size_t)drow * N + gn],     v0);
                    atomicAdd(&C[(size_t)drow * N + gn + 1], v1);
                } else {
                    *(float2*)&C[(size_t)gm * N + gn] = make_float2(v0, v1);
                }
            }
        }
    }
}

// ---------------- edge bracket, transposed-edge layout (R15 proven) ----------------
constexpr int TEB = 32;
constexpr int BRS = 33;
constexpr uint32_t BR_TILE = D_ * BRS;
constexpr uint32_t BR_SMEM = (3 * BR_TILE + 4 * NNZ_) * 4;

__global__ __launch_bounds__(256) void edge_bracket_T(
    const float* __restrict__ h, const int* __restrict__ ei,
    const int* __restrict__ sci, const int* __restrict__ scj,
    const int* __restrict__ sck, const float* __restrict__ scc,
    float* __restrict__ br)
{
    extern __shared__ float sm[];
    float* hsT = sm;
    float* hdT = sm + BR_TILE;
    float* brT = sm + 2 * BR_TILE;
    int*   s_i = (int*)(sm + 3 * BR_TILE);
    int*   s_j = s_i + NNZ_;
    int*   s_k = s_j + NNZ_;
    float* s_c = (float*)(s_k + NNZ_);

    const int tid = threadIdx.x;
    for (int t = tid; t < NNZ_; t += 256) {
        s_i[t] = __ldg(&sci[t]);
        s_j[t] = __ldg(&scj[t]);
        s_k[t] = __ldg(&sck[t]);
        s_c[t] = __ldg(&scc[t]);
    }
    for (int q = tid; q < (int)BR_TILE; q += 256) brT[q] = 0.0f;

    const int e   = tid >> 3;
    const int sub = tid & 7;
    const int eg  = blockIdx.x * TEB + e;
    const int sn  = __ldg(&ei[eg]);
    const int dn  = __ldg(&ei[E_ + eg]);
    const float4* hs4 = (const float4*)(h + (size_t)sn * D_);
    const float4* hd4 = (const float4*)(h + (size_t)dn * D_);
    #pragma unroll
    for (int j = 0; j < 8; j++) {
        const int q4 = sub + j * 8;
        if (q4 < D_ / 4) {
            float4 a = hs4[q4];
            float4 b = hd4[q4];
            const int d = q4 * 4;
            hsT[(d + 0) * BRS + e] = a.x;
            hsT[(d + 1) * BRS + e] = a.y;
            hsT[(d + 2) * BRS + e] = a.z;
            hsT[(d + 3) * BRS + e] = a.w;
            hdT[(d + 0) * BRS + e] = b.x;
            hdT[(d + 1) * BRS + e] = b.y;
            hdT[(d + 2) * BRS + e] = b.z;
            hdT[(d + 3) * BRS + e] = b.w;
        }
    }
    __syncthreads();

    const int w = tid >> 5, lane = tid & 31;
    for (int t = w * 64; t < w * 64 + 64; t++) {
        const float v = s_c[t] * hsT[s_i[t] * BRS + lane] * hdT[s_j[t] * BRS + lane];
        atomicAdd(&brT[s_k[t] * BRS + lane], v);
    }
    __syncthreads();

    float4* brow = (float4*)(br + (size_t)eg * D_);
    #pragma unroll
    for (int j = 0; j < 8; j++) {
        const int q4 = sub + j * 8;
        if (q4 < D_ / 4) {
            const int d = q4 * 4;
            brow[q4] = make_float4(brT[(d + 0) * BRS + e], brT[(d + 1) * BRS + e],
                                   brT[(d + 2) * BRS + e], brT[(d + 3) * BRS + e]);
        }
    }
}

__global__ void zero_kernel(float* __restrict__ p, size_t n) {
    size_t idx = (size_t)blockIdx.x * blockDim.x + threadIdx.x;
    if (idx < n) p[idx] = 0.0f;
}

// ---------------- killing form + pooling (scatter to graphs) ----------------
__global__ __launch_bounds__(128) void killing_pool_kernel(
    const float* __restrict__ h, const int* __restrict__ batch,
    const int* __restrict__ kbr, const int* __restrict__ kbc,
    const float* __restrict__ kbv,
    float* __restrict__ pooled, float* __restrict__ cnt)
{
    const int n = blockIdx.x;
    __shared__ float hrow[D_];
    __shared__ float wsum[4];
    for (int k = threadIdx.x; k < D_; k += 128)
        hrow[k] = h[(size_t)n * D_ + k];
    __syncthreads();

    float s = 0.0f;
    for (int t = threadIdx.x; t < NB_; t += 128)
        s += __ldg(&kbv[t]) * hrow[__ldg(&kbr[t])] * hrow[__ldg(&kbc[t])];
    #pragma unroll
    for (int off = 16; off > 0; off >>= 1)
        s += __shfl_down_sync(0xffffffffu, s, off);
    if ((threadIdx.x & 31) == 0) wsum[threadIdx.x >> 5] = s;
    __syncthreads();

    const int b = __ldg(&batch[n]);
    for (int k = threadIdx.x; k < D_; k += 128)
        atomicAdd(&pooled[b * DP1_ + k], hrow[k]);
    if (threadIdx.x == 0) {
        float ks = wsum[0] + wsum[1] + wsum[2] + wsum[3];
        atomicAdd(&pooled[b * DP1_ + D_], ks);
        atomicAdd(&cnt[b], 1.0f);
    }
}

// ---------------- final MLP per graph ----------------
__global__ __launch_bounds__(256) void final_mlp_kernel(
    const float* __restrict__ pooled, const float* __restrict__ cnt,
    const float* __restrict__ Wo1, const float* __restrict__ bo1,
    const float* __restrict__ Wo2, const float* __restrict__ bo2,
    float* __restrict__ out)
{
    const int g = blockIdx.x;
    __shared__ float p[DP1_];
    __shared__ float hid[HID_];
    const float c = fmaxf(cnt[g], 1.0f);
    for (int k = threadIdx.x; k < DP1_; k += 256)
        p[k] = pooled[g * DP1_ + k] / c;
    __syncthreads();

    const int j = threadIdx.x;
    float s = __ldg(&bo1[j]);
    for (int k = 0; k < DP1_; k++)
        s = fmaf(p[k], __ldg(&Wo1[k * HID_ + j]), s);
    hid[j] = silu_f(s);
    __syncthreads();

    if (j < OUT_) {
        float o = __ldg(&bo2[j]);
        for (int k = 0; k < HID_; k++)
            o = fmaf(hid[k], __ldg(&Wo2[k * OUT_ + j]), o);
        out[g * OUT_ + j] = o;
    }
}

// ---------------- host driver ----------------
static inline dim3 gemm_grid(int M, int N) {
    return dim3((N + BN - 1) / BN, (M + BM - 1) / BM);
}

extern "C" void kernel_launch(void* const* d_in, const int* in_sizes, int n_in,
                              void* d_out, int out_size)
{
    const float* x     = (const float*)d_in[0];
    const int*   ei    = (const int*)  d_in[1];
    const int*   batch = (const int*)  d_in[2];
    const int*   sci   = (const int*)  d_in[3];
    const int*   scj   = (const int*)  d_in[4];
    const int*   sck   = (const int*)  d_in[5];
    const float* scc   = (const float*)d_in[6];
    const int*   kbr   = (const int*)  d_in[7];
    const int*   kbc   = (const int*)  d_in[8];
    const float* kbv   = (const float*)d_in[9];
    const float* Wi1   = (const float*)d_in[10];
    const float* bi1   = (const float*)d_in[11];
    const float* Wi2   = (const float*)d_in[12];
    const float* bi2   = (const float*)d_in[13];
    const float* msgW1 = (const float*)d_in[14];
    const float* msgb1 = (const float*)d_in[15];
    const float* msgW2 = (const float*)d_in[16];
    const float* msgb2 = (const float*)d_in[17];
    const float* updW1 = (const float*)d_in[18];
    const float* updb1 = (const float*)d_in[19];
    const float* updW2 = (const float*)d_in[20];
    const float* updb2 = (const float*)d_in[21];
    const float* Wo1   = (const float*)d_in[22];
    const float* bo1   = (const float*)d_in[23];
    const float* Wo2   = (const float*)d_in[24];
    const float* bo2   = (const float*)d_in[25];

    float *t1, *h, *br, *eH, *agg, *pooled, *cnt, *zbias;
    uint32_t *wpHi, *wpLo;
    cudaGetSymbolAddress((void**)&t1,     g_t1);
    cudaGetSymbolAddress((void**)&h,      g_h);
    cudaGetSymbolAddress((void**)&br,     g_br);
    cudaGetSymbolAddress((void**)&eH,     g_eH);
    cudaGetSymbolAddress((void**)&agg,    g_agg);
    cudaGetSymbolAddress((void**)&pooled, g_pooled);
    cudaGetSymbolAddress((void**)&cnt,    g_cnt);
    cudaGetSymbolAddress((void**)&zbias,  g_zbias);
    cudaGetSymbolAddress((void**)&wpHi,   g_wpHiW);
    cudaGetSymbolAddress((void**)&wpLo,   g_wpLoW);

    cudaFuncSetAttribute(edge_bracket_T,
                         cudaFuncAttributeMaxDynamicSharedMemorySize, (int)BR_SMEM);

    const int* src = ei;
    const int* dst = ei + E_;

    // side stream + events for per-layer fork/join (host objects only; created
    // per call -- kernel_launch runs ~3x total, leak is bounded and legal)
    cudaStream_t s2;
    cudaStreamCreateWithFlags(&s2, cudaStreamNonBlocking);
    cudaEvent_t evFork[NL_], evJoin[NL_];
    for (int l = 0; l < NL_; l++) {
        cudaEventCreateWithFlags(&evFork[l], cudaEventDisableTiming);
        cudaEventCreateWithFlags(&evJoin[l], cudaEventDisableTiming);
    }

    // ---- build prepack table (22 segments) and launch once ----
    WSrcTab tab;
    long long offs[NSEG];
    {
        int s = 0;
        auto put = [&](const float* p, int ko, int K, int N, int Kp) {
            tab.p[s] = p; tab.ko[s] = ko; tab.K[s] = K; tab.N[s] = N;
            tab.words[s] = (long long)(Kp / 2) * N;
            s++;
        };
        put(Wi1, 0, IN_,  HID_, 128);
        put(Wi2, 0, HID_, D_,   256);
        for (int l = 0; l < NL_; l++) {
            const float* mW1 = msgW1 + (size_t)l * D2_ * HID_;
            const float* mW2 = msgW2 + (size_t)l * HID_ * D_;
            const float* uW1 = updW1 + (size_t)l * D2_ * HID_;
            const float* uW2 = updW2 + (size_t)l * HID_ * D_;
            put(mW1, 0,   D_,   HID_, 256);
            put(mW1, D_,  D_,   HID_, 256);
            put(mW2, 0,   HID_, D_,   256);
            put(uW1, 0,   D2_,  HID_, 512);
            put(uW2, 0,   HID_, D_,   256);
        }
        long long run = 0;
        for (int i = 0; i < NSEG; i++) { offs[i] = run; run += tab.words[i]; }
    }
    {
        long long nb = ((long long)WP_WORDS + 255) / 256;
        prepack_all_kernel<<<(unsigned)nb, 256>>>(tab);
    }
    zero_kernel<<<1, HID_>>>(zbias, HID_);

    const long long oWi1 = offs[0], oWi2 = offs[1];

    // ---- input MLP ----
    gemm_3xbf16<<<gemm_grid(N_, HID_), 256>>>(
        x,  nullptr, x,  IN_,  wpHi + oWi1, wpLo + oWi1, bi1,
        nullptr, nullptr, nullptr, t1, N_, HID_, IN_,  128, 1);
    gemm_3xbf16<<<gemm_grid(N_, D_),   256>>>(
        t1, nullptr, t1, HID_, wpHi + oWi2, wpLo + oWi2, bi2,
        nullptr, nullptr, nullptr, h,  N_, D_,   HID_, 256, 0);

    // ---- message passing layers ----
    for (int l = 0; l < NL_; l++) {
        const long long oA  = offs[2 + l * 5 + 0];
        const long long oB  = offs[2 + l * 5 + 1];
        const long long oM2 = offs[2 + l * 5 + 2];
        const long long oU1 = offs[2 + l * 5 + 3];
        const long long oU2 = offs[2 + l * 5 + 4];
        const float* mb1 = msgb1 + (size_t)l * HID_;
        const float* mb2 = msgb2 + (size_t)l * D_;
        const float* ub1 = updb1 + (size_t)l * HID_;
        const float* ub2 = updb2 + (size_t)l * D_;

        // fork: side stream runs hw GEMM + agg zero while main runs the bracket
        cudaEventRecord(evFork[l], 0);
        cudaStreamWaitEvent(s2, evFork[l], 0);

        // s2: node-level half of message MLP1: hw = h @ mW1[0:D] + mb1
        gemm_3xbf16<<<gemm_grid(N_, HID_), 256, 0, s2>>>(
            h, nullptr, h, D_, wpHi + oA, wpLo + oA, mb1,
            nullptr, nullptr, nullptr, t1, N_, HID_, D_, 256, 0);
        // s2: zero agg (read of previous agg finished before fork on stream 0)
        {
            size_t n = (size_t)N_ * D_;
            zero_kernel<<<(unsigned)((n + 255) / 256), 256, 0, s2>>>(agg, n);
        }
        cudaEventRecord(evJoin[l], s2);

        // main: edge bracket
        edge_bracket_T<<<E_ / TEB, 256, BR_SMEM>>>(h, ei, sci, scj, sck, scc, br);

        // join: eH needs hw (s2) + br (main); scatter needs zeroed agg (s2)
        cudaStreamWaitEvent(0, evJoin[l], 0);

        // edge-level half: eH = silu(br @ mW1[D:2D] + hw[src])
        gemm_3xbf16<<<gemm_grid(E_, HID_), 256>>>(
            br, nullptr, br, D_, wpHi + oB, wpLo + oB, zbias,
            t1, src, nullptr, eH, E_, HID_, D_, 256, 1);

        // message MLP2 with fused scatter-add into agg
        gemm_3xbf16<<<gemm_grid(E_, D_), 256>>>(
            eH, nullptr, eH, HID_, wpHi + oM2, wpLo + oM2, mb2,
            nullptr, nullptr, dst, agg, E_, D_, HID_, 256, 0);

        // update MLP: A = [h | agg]
        gemm_3xbf16<<<gemm_grid(N_, HID_), 256>>>(
            h,  nullptr, agg, D_,  wpHi + oU1, wpLo + oU1, ub1,
            nullptr, nullptr, nullptr, t1, N_, HID_, D2_, 512, 1);
        gemm_3xbf16<<<gemm_grid(N_, D_),   256>>>(
            t1, nullptr, t1,  HID_, wpHi + oU2, wpLo + oU2, ub2,
            h, nullptr, nullptr, h,  N_, D_,   HID_, 256, 0);
    }

    // ---- killing form + pooling ----
    {
        size_t n = NG_ * DP1_;
        zero_kernel<<<(unsigned)((n + 255) / 256), 256>>>(pooled, n);
        zero_kernel<<<1, NG_>>>(cnt, NG_);
    }
    killing_pool_kernel<<<N_, 128>>>(h, batch, kbr, kbc, kbv, pooled, cnt);

    // ---- final MLP ----
    final_mlp_kernel<<<NG_, 256>>>(pooled, cnt, Wo1, bo1, Wo2, bo2, (float*)d_out);
}